// round 12
// baseline (speedup 1.0000x reference)
#include <cuda_runtime.h>
#include <cuda.h>
#include <cuda_bf16.h>
#include <cstdint>

#define Bn 2
#define Ln 4096
#define Mn (Bn*Ln)          // 8192 rows
#define HIDn 2048
#define ENGn 1024
#define NHEADn 16
#define VOCABn 129280
#define HCn 4
#define NTOT 10240          // 2048 value cols + 4*2048 key cols
#define EPS_RMS 1.1920929e-07f
#define EPS_SC  1e-5f

#if defined(__CUDA_ARCH__) && (__CUDA_ARCH__ == 1030) && defined(__CUDA_ARCH_FEAT_SM103_ALL)
#define USE_TC 1
#else
#define USE_TC 0
#endif

// ---------------- scratch (device globals: allocation-free) ----------------
__device__ __nv_bfloat16 g_embh[(size_t)Mn * ENGn];
__device__ __nv_bfloat16 g_embl[(size_t)Mn * ENGn];
__device__ __nv_bfloat16 g_wth [(size_t)NTOT * ENGn];  // W^T hi (keys hc-interleaved)
__device__ __nv_bfloat16 g_wtl [(size_t)NTOT * ENGn];  // W^T lo (key rows stay zero)
__device__ float g_vp [(size_t)Mn * HIDn];
__device__ float g_invq[Mn];
__device__ float g_vsq [Mn * 16];
__device__ float g_pnum[Mn * HCn * 16];
__device__ float g_psq [Mn * HCn * 16];
__device__ float g_alpha[Mn * HCn];
__device__ float g_sgate[Mn];

__device__ __forceinline__ uint32_t sm2u(const void* p) {
    return (uint32_t)__cvta_generic_to_shared(p);
}

// ---------------- K1: gather -> bf16 hi/lo + hidden row rms ----------------
__global__ void k_gather(const void* __restrict__ ids_raw,
                         const float* __restrict__ tab,
                         const float* __restrict__ hid)
{
    const int row = blockIdx.x;
    const int tid = threadIdx.x;
    __shared__ int   sid[NHEADn];
    __shared__ float sbuf[32];

    if (tid == 0) {
        const long long* p64 = (const long long*)ids_raw;
        bool is64 = true;
        #pragma unroll
        for (int i = 0; i < 8; i++) {
            long long v = p64[i];
            if (v < 0 || v >= (long long)VOCABn) { is64 = false; break; }
        }
        if (is64) {
            const long long* p = p64 + (size_t)row * NHEADn;
            for (int h = 0; h < NHEADn; h++) sid[h] = (int)p[h];
        } else {
            const int* p = ((const int*)ids_raw) + (size_t)row * NHEADn;
            for (int h = 0; h < NHEADn; h++) sid[h] = p[h];
        }
    }
    __syncthreads();

    #pragma unroll
    for (int e = tid; e < ENGn; e += 256) {
        int h = e >> 6, d = e & 63;
        float v = tab[((size_t)h * VOCABn + (size_t)sid[h]) * 64 + d];
        __nv_bfloat16 hi = __float2bfloat16(v);
        __nv_bfloat16 lo = __float2bfloat16(v - __bfloat162float(hi));
        g_embh[(size_t)row * ENGn + e] = hi;
        g_embl[(size_t)row * ENGn + e] = lo;
    }

    float s = 0.f;
    const float* hr = hid + (size_t)row * HIDn;
    for (int i = tid; i < HIDn; i += 256) { float v = hr[i]; s += v * v; }
    {
        int lane = tid & 31, wid = tid >> 5;
        #pragma unroll
        for (int q = 16; q > 0; q >>= 1) s += __shfl_down_sync(0xffffffffu, s, q);
        if (lane == 0) sbuf[wid] = s;
        __syncthreads();
        if (wid == 0) {
            s = (lane < 8) ? sbuf[lane] : 0.f;
            #pragma unroll
            for (int q = 4; q > 0; q >>= 1) s += __shfl_down_sync(0xffffffffu, s, q);
            if (lane == 0) g_invq[row] = rsqrtf(s * (1.f / HIDn) + EPS_RMS);
        }
    }
}

// ---------------- K2: weight transpose + bf16 hi/lo split ----------------
// value rows: hi+lo. key rows (hc-interleaved n' = 2048 + (d>>7)*512 + hc*128
// + (d&127)): hi ONLY — keys GEMM is pure bf16.
__global__ void k_wt(const float* __restrict__ vw, const float* __restrict__ kw)
{
    __shared__ float ts[64][65];
    const int n0 = blockIdx.x * 64;
    const int k0 = blockIdx.y * 64;
    const int s  = n0 >> 11;
    const float* W = (s == 0) ? vw : kw + (size_t)(s - 1) * ENGn * HIDn;
    const int col0 = n0 & 2047;
    const int tx  = threadIdx.x & 63;
    const int ty4 = threadIdx.x >> 6;

    #pragma unroll
    for (int i = 0; i < 16; i++) {
        int kk = ty4 + i * 4;
        ts[kk][tx] = W[(size_t)(k0 + kk) * HIDn + col0 + tx];
    }
    __syncthreads();
    #pragma unroll
    for (int i = 0; i < 16; i++) {
        int nn = ty4 + i * 4;
        float v = ts[tx][nn];
        __nv_bfloat16 hi = __float2bfloat16(v);
        if (s == 0) {
            int orow = n0 + nn;
            size_t o = (size_t)orow * ENGn + k0 + tx;
            g_wth[o] = hi;
            g_wtl[o] = __float2bfloat16(v - __bfloat162float(hi));
        } else {
            int d = col0 + nn;
            int orow = 2048 + ((d >> 7) << 9) + ((s - 1) << 7) + (d & 127);
            g_wth[(size_t)orow * ENGn + k0 + tx] = hi;   // lo stays zero
        }
    }
}

// ================= tcgen05 path (sm_103a feature target) =====================
// cluster pair computes D[256 M, 512 N] over K=1024; 16 kchunks of 64.
// value tiles (nsup<4): 3-term bf16x3 (96KB/chunk, 24 MMAs).
// key tiles: PURE bf16 (AhBh only): 48KB/chunk, 8 MMAs, no fullB barrier.
#define STAGE_B 98304
#define GSMEM   (1024 + 2 * STAGE_B)

#if USE_TC
__device__ __forceinline__ uint64_t mk_desc(uint32_t addr) {
    // SW128, Blackwell version=1, LBO=1, SBO=64 (K-major, 128B rows)
    return 0x4000404000010000ull | (uint64_t)((addr >> 4) & 0x3FFF);
}
__device__ __forceinline__ void mbar_wait(uint32_t a, int ph) {
    asm volatile(
        "{\n\t.reg .pred P;\n\t"
        "W_%=:\n\t"
        "mbarrier.try_wait.parity.acquire.cluster.shared::cta.b64 P, [%0], %1, 0x989680;\n\t"
        "@P bra.uni D_%=;\n\t"
        "bra.uni W_%=;\n\t"
        "D_%=:\n\t}"
        :: "r"(a), "r"(ph) : "memory");
}
__device__ __forceinline__ void remote_arrive(uint32_t a) {
    uint32_t zero = 0;
    asm volatile(
        "{\n\t.reg .b32 ra;\n\t"
        "mapa.shared::cluster.u32 ra, %0, %1;\n\t"
        "mbarrier.arrive.shared::cluster.b64 _, [ra];\n\t}"
        :: "r"(a), "r"(zero) : "memory");
}
__device__ __forceinline__ void mma_f16_cg2(uint32_t d, uint64_t da, uint64_t db,
                                            uint32_t idesc, bool en) {
    uint32_t e = en ? 1u : 0u, z = 0u;
    asm volatile(
        "{\n\t.reg .pred p;\n\t"
        "setp.ne.u32 p, %5, 0;\n\t"
        "tcgen05.mma.cta_group::2.kind::f16 [%0], %1, %2, %3, "
        "{%4, %4, %4, %4, %4, %4, %4, %4}, p;\n\t}"
        :: "r"(d), "l"(da), "l"(db), "r"(idesc), "r"(z), "r"(e) : "memory");
}
#define TC_LD32(r, a) \
    asm volatile("tcgen05.ld.sync.aligned.32x32b.x32.b32 " \
        "{%0, %1, %2, %3, %4, %5, %6, %7, %8, %9, %10, %11, %12, %13, %14, %15, " \
        "%16, %17, %18, %19, %20, %21, %22, %23, %24, %25, %26, %27, %28, %29, %30, %31}, [%32];" \
        : "=r"((r)[0]), "=r"((r)[1]), "=r"((r)[2]), "=r"((r)[3]), \
          "=r"((r)[4]), "=r"((r)[5]), "=r"((r)[6]), "=r"((r)[7]), \
          "=r"((r)[8]), "=r"((r)[9]), "=r"((r)[10]), "=r"((r)[11]), \
          "=r"((r)[12]), "=r"((r)[13]), "=r"((r)[14]), "=r"((r)[15]), \
          "=r"((r)[16]), "=r"((r)[17]), "=r"((r)[18]), "=r"((r)[19]), \
          "=r"((r)[20]), "=r"((r)[21]), "=r"((r)[22]), "=r"((r)[23]), \
          "=r"((r)[24]), "=r"((r)[25]), "=r"((r)[26]), "=r"((r)[27]), \
          "=r"((r)[28]), "=r"((r)[29]), "=r"((r)[30]), "=r"((r)[31]) \
        : "r"(a))
#define TC_WAIT_LD() asm volatile("tcgen05.wait::ld.sync.aligned;" ::: "memory")
#define TMA2D(dst, map, x, y, bar) \
    asm volatile("cp.async.bulk.tensor.2d.shared::cta.global.tile" \
                 ".mbarrier::complete_tx::bytes [%0], [%1, {%2, %3}], [%4];" \
                 :: "r"(dst), "l"(map), "r"(x), "r"(y), "r"(bar) : "memory")
#define MBAR_EXPECT(bar, bytes) \
    asm volatile("mbarrier.arrive.expect_tx.shared.b64 _, [%0], %1;" \
                 :: "r"(bar), "r"(bytes) : "memory")
#endif

__global__ void __launch_bounds__(256, 1) __cluster_dims__(2, 1, 1)
k_tcgemm(const __grid_constant__ CUtensorMap tmAh,
         const __grid_constant__ CUtensorMap tmAl,
         const __grid_constant__ CUtensorMap tmBh,
         const __grid_constant__ CUtensorMap tmBl,
         const float* __restrict__ vb, const float* __restrict__ kb,
         const float* __restrict__ n1, const float* __restrict__ n2,
         const float* __restrict__ hid)
{
#if !USE_TC
    (void)vb; (void)kb; (void)n1; (void)n2; (void)hid;
    return;
#else
    extern __shared__ char sm[];
    const int tid  = threadIdx.x;
    const int rank = blockIdx.x & 1;
    const int m0   = (blockIdx.x >> 1) * 256;
    const int nsup = blockIdx.y;                       // 0..19
    const bool isKey = (nsup >= 4);
    const uint32_t sb = sm2u(sm);
    // barriers: fullA[2]@16, fullB[2]@32, relA[2]@48, relB[2]@64, done[2]@80
    const uint32_t mb_fullA = sb + 16;
    const uint32_t mb_fullB = sb + 32;
    const uint32_t mb_relA  = sb + 48;
    const uint32_t mb_relB  = sb + 64;
    const uint32_t mb_done  = sb + 80;

    if (tid == 0) {
        #pragma unroll
        for (int s = 0; s < 2; s++) {
            asm volatile("mbarrier.init.shared.b64 [%0], 1;" :: "r"(mb_fullA + s * 8) : "memory");
            asm volatile("mbarrier.init.shared.b64 [%0], 1;" :: "r"(mb_fullB + s * 8) : "memory");
            asm volatile("mbarrier.init.shared.b64 [%0], 1;" :: "r"(mb_relA  + s * 8) : "memory");
            asm volatile("mbarrier.init.shared.b64 [%0], 1;" :: "r"(mb_relB  + s * 8) : "memory");
            asm volatile("mbarrier.init.shared.b64 [%0], 1;" :: "r"(mb_done  + s * 8) : "memory");
        }
    }
    if (tid < 32) {
        asm volatile("tcgen05.alloc.cta_group::2.sync.aligned.shared::cta.b32 [%0], 512;"
                     :: "r"(sb) : "memory");
    }
    __syncthreads();
    uint32_t tmem;
    asm volatile("ld.shared.b32 %0, [%1];" : "=r"(tmem) : "r"(sb));
    asm volatile("barrier.cluster.arrive.aligned;" ::: "memory");
    asm volatile("barrier.cluster.wait.aligned;"   ::: "memory");

    const uint32_t idesc = (1u << 4) | (1u << 7) | (1u << 10)
                         | ((256u / 8) << 17) | ((256u / 16) << 24);

    if (tid == 0) {
        const int ar  = m0 + rank * 128;                // A row base
        const int br0 = nsup * 512 + rank * 128;        // B rows half 0
        const int br1 = nsup * 512 + 256 + rank * 128;  // B rows half 1
        int fphA[2] = {0,0}, fphB[2] = {0,0};
        int rphA[2] = {0,0}, rphB[2] = {0,0};
        int dph [2] = {0,0};

        auto issue = [&](int kc, int s) {
            const uint32_t d0 = sb + 1024 + s * STAGE_B;
            const int x = kc * 128;
            // A-half: Ah + Bh (48KB) -> fullA
            MBAR_EXPECT(mb_fullA + s * 8, 49152u);
            TMA2D(d0,          &tmAh, x, ar,  mb_fullA + s * 8);
            TMA2D(d0 + 32768,  &tmBh, x, br0, mb_fullA + s * 8);
            TMA2D(d0 + 49152,  &tmBh, x, br1, mb_fullA + s * 8);
            // B-half (value tiles only): Al + Bl -> fullB
            if (!isKey) {
                MBAR_EXPECT(mb_fullB + s * 8, 49152u);
                TMA2D(d0 + 16384,  &tmAl, x, ar,  mb_fullB + s * 8);
                TMA2D(d0 + 65536,  &tmBl, x, br0, mb_fullB + s * 8);
                TMA2D(d0 + 81920,  &tmBl, x, br1, mb_fullB + s * 8);
            }
        };
        auto compute = [&](int kc, int sp) {
            if (rank == 0) {
                mbar_wait(mb_fullA + sp * 8, fphA[sp]); fphA[sp] ^= 1;
                mbar_wait(mb_relA  + sp * 8, rphA[sp]); rphA[sp] ^= 1;
                const uint32_t a = sb + 1024 + sp * STAGE_B;
                const uint64_t dAh = mk_desc(a);
                #pragma unroll
                for (int h = 0; h < 2; h++) {
                    const uint64_t dBh = mk_desc(a + 32768 + h * 16384);
                    const uint32_t dst = tmem + h * 256;
                    #pragma unroll
                    for (int ks = 0; ks < 4; ks++)
                        mma_f16_cg2(dst, dAh + ks * 2, dBh + ks * 2, idesc,
                                    !(kc == 0 && ks == 0));
                }
                if (!isKey) {
                    mbar_wait(mb_fullB + sp * 8, fphB[sp]); fphB[sp] ^= 1;
                    mbar_wait(mb_relB  + sp * 8, rphB[sp]); rphB[sp] ^= 1;
                    const uint64_t dAl = mk_desc(a + 16384);
                    #pragma unroll
                    for (int h = 0; h < 2; h++) {
                        const uint64_t dBh = mk_desc(a + 32768 + h * 16384);
                        const uint64_t dBl = mk_desc(a + 65536 + h * 16384);
                        const uint32_t dst = tmem + h * 256;
                        #pragma unroll
                        for (int ks = 0; ks < 4; ks++) {
                            mma_f16_cg2(dst, dAh + ks * 2, dBl + ks * 2, idesc, true);
                            mma_f16_cg2(dst, dAl + ks * 2, dBh + ks * 2, idesc, true);
                        }
                    }
                }
                asm volatile(
                    "tcgen05.commit.cta_group::2.mbarrier::arrive::one.shared::cluster"
                    ".multicast::cluster.b64 [%0], %1;"
                    :: "r"(mb_done + sp * 8), "h"((uint16_t)3) : "memory");
            } else {
                mbar_wait(mb_fullA + sp * 8, fphA[sp]); fphA[sp] ^= 1;
                remote_arrive(mb_relA + sp * 8);
                if (!isKey) {
                    mbar_wait(mb_fullB + sp * 8, fphB[sp]); fphB[sp] ^= 1;
                    remote_arrive(mb_relB + sp * 8);
                }
            }
        };

        #pragma unroll 1
        for (int kc = 0; kc < 16; kc++) {
            const int s = kc & 1;
            if (kc >= 2) { mbar_wait(mb_done + s * 8, dph[s]); dph[s] ^= 1; }
            issue(kc, s);
            if (kc >= 1) compute(kc - 1, s ^ 1);
        }
        compute(15, 1);
        mbar_wait(mb_done + 8, dph[1]);   // all 16 chunks' MMAs retired
    }
    __syncthreads();
    asm volatile("tcgen05.fence::after_thread_sync;" ::: "memory");

    // -------- coalesced epilogue (per-warp 32x33 SMEM transpose tile) --------
    const int w = tid >> 5, lane = tid & 31;
    const int h  = w >> 2;                      // col half (0: 0-255, 1: 256-511)
    const int rg = w & 3;                       // row group within CTA
    const int r0 = m0 + rank * 128 + rg * 32;
    const int r  = r0 + lane;
    float* tile = (float*)(sm + 1024) + w * (32 * 33);

    if (nsup < 4) {
        // ---- value projection: vp = D + vb, accumulate sum(vp^2) ----
        float vsq = 0.f;
        const int nb0 = nsup * 512 + h * 256;
        #pragma unroll
        for (int q = 0; q < 8; q++) {
            uint32_t d[32];
            TC_LD32(d, tmem + h * 256 + q * 32);
            TC_WAIT_LD();
            const int nb = nb0 + q * 32;
            #pragma unroll
            for (int c = 0; c < 32; c++) {
                float o = __uint_as_float(d[c]) + __ldg(vb + nb + c);
                vsq = fmaf(o, o, vsq);
                tile[lane * 33 + c] = o;
            }
            __syncwarp();
            #pragma unroll
            for (int rr = 0; rr < 32; rr++)
                g_vp[(size_t)(r0 + rr) * HIDn + nb + lane] = tile[rr * 33 + lane];
            __syncwarp();
        }
        g_vsq[r * 16 + nsup * 2 + h] = vsq;
    } else {
        // ---- keys (hc-interleaved): reduce to gate partials ----
        const int q = nsup - 4;                  // 0..15 d-chunk
        float pn[2] = {0.f, 0.f}, ps[2] = {0.f, 0.f};
        #pragma unroll
        for (int dq = 0; dq < 4; dq++) {
            const int dwin = q * 128 + dq * 32;
            #pragma unroll
            for (int rr = 0; rr < 32; rr++)      // coalesced hid stage
                tile[rr * 33 + lane] = __ldg(hid + (size_t)(r0 + rr) * HIDn + dwin + lane);
            __syncwarp();
            #pragma unroll
            for (int hcl = 0; hcl < 2; hcl++) {
                const int hc = h * 2 + hcl;
                uint32_t d[32];
                TC_LD32(d, tmem + h * 256 + hcl * 128 + dq * 32);
                TC_WAIT_LD();
                const int nb = hc * HIDn + dwin;
                #pragma unroll
                for (int c = 0; c < 32; c++) {
                    float kv = __uint_as_float(d[c]) + __ldg(kb + nb + c);
                    float w12 = __ldg(n1 + nb + c) * __ldg(n2 + nb + c);
                    pn[hcl] = fmaf(kv * w12, tile[lane * 33 + c], pn[hcl]);
                    ps[hcl] = fmaf(kv, kv, ps[hcl]);
                }
            }
            __syncwarp();
        }
        #pragma unroll
        for (int hcl = 0; hcl < 2; hcl++) {
            const int hc = h * 2 + hcl;
            g_pnum[((size_t)r * HCn + hc) * 16 + q] = pn[hcl];
            g_psq [((size_t)r * HCn + hc) * 16 + q] = ps[hcl];
        }
    }

    __syncthreads();
    if (tid < 32) {
        asm volatile("tcgen05.relinquish_alloc_permit.cta_group::2.sync.aligned;");
        asm volatile("tcgen05.dealloc.cta_group::2.sync.aligned.b32 %0, 512;" :: "r"(tmem));
    }
    asm volatile("barrier.cluster.arrive.aligned;" ::: "memory");
    asm volatile("barrier.cluster.wait.aligned;"   ::: "memory");
#endif
}

// ============ fallback: mma.sync bf16x3 pipelined GEMM (plain sm_103) ========
// (dead on sm_103a; key-row lo weights are zero so extra terms add 0)
#define FB_STAGE 40960
#define FB_SMEM  (3 * FB_STAGE)

#define LDSM4(r, addr) \
    asm volatile("ldmatrix.sync.aligned.m8n8.x4.shared.b16 {%0,%1,%2,%3}, [%4];" \
        : "=r"((r)[0]), "=r"((r)[1]), "=r"((r)[2]), "=r"((r)[3]) : "r"(addr))

#define MMA16816(c, a, b) \
    asm volatile("mma.sync.aligned.m16n8k16.row.col.f32.bf16.bf16.f32 " \
        "{%0,%1,%2,%3}, {%4,%5,%6,%7}, {%8,%9}, {%0,%1,%2,%3};" \
        : "+f"((c)[0]), "+f"((c)[1]), "+f"((c)[2]), "+f"((c)[3]) \
        : "r"((a)[0]), "r"((a)[1]), "r"((a)[2]), "r"((a)[3]), \
          "r"((b)[0]), "r"((b)[1]))

__global__ void __launch_bounds__(256, 1)
k_gemm_fb(const float* __restrict__ vb, const float* __restrict__ kb,
          const float* __restrict__ n1, const float* __restrict__ n2,
          const float* __restrict__ hid)
{
#if USE_TC
    (void)vb; (void)kb; (void)n1; (void)n2; (void)hid;
    return;
#else
    extern __shared__ char smem[];
    const uint32_t sb = sm2u(smem);
    const int tid = threadIdx.x;
    const int ntile = blockIdx.x;
    const int m0 = blockIdx.y * 128;
    const int n0 = ntile * 128;

    const char* gA_h = (const char*)(g_embh + (size_t)m0 * ENGn);
    const char* gA_l = (const char*)(g_embl + (size_t)m0 * ENGn);
    const char* gB_h = (const char*)(g_wth + (size_t)n0 * ENGn);
    const char* gB_l = (const char*)(g_wtl + (size_t)n0 * ENGn);

    const int ch = tid & 3;
    auto load_stage = [&](int s, int kc) {
        #pragma unroll
        for (int i = 0; i < 8; i++) {
            const int tsel = i >> 1;
            const int row = (((i & 1) << 8) + tid) >> 2;
            const char* src = (tsel == 0 ? gA_h : tsel == 1 ? gA_l :
                               tsel == 2 ? gB_h : gB_l)
                              + (size_t)row * 2048 + kc * 64 + ch * 16;
            uint32_t d = sb + s * FB_STAGE + tsel * 10240 + row * 80 + ch * 16;
            asm volatile("cp.async.cg.shared.global [%0], [%1], 16;"
                         :: "r"(d), "l"(src));
        }
        asm volatile("cp.async.commit_group;" ::: "memory");
    };

    load_stage(0, 0);
    load_stage(1, 1);

    float acc[4][4][4];
    #pragma unroll
    for (int i = 0; i < 4; i++)
        #pragma unroll
        for (int j = 0; j < 4; j++)
            #pragma unroll
            for (int q = 0; q < 4; q++) acc[i][j][q] = 0.f;

    const int lane = tid & 31, w = tid >> 5;
    const int wm = w >> 2, wn = w & 3;
    const uint32_t aRow   = wm * 64 + (lane & 15);
    const uint32_t aChunk = (lane >> 4) * 16;
    const int g = lane >> 3;
    const uint32_t bRow   = wn * 32 + ((g >> 1) & 1) * 8 + (lane & 7);
    const uint32_t bChunk = (g & 1) * 16;

    for (int kt = 0; kt < 32; kt++) {
        if (kt + 2 < 32) load_stage((kt + 2) % 3, kt + 2);
        else asm volatile("cp.async.commit_group;" ::: "memory");
        asm volatile("cp.async.wait_group 2;" ::: "memory");
        __syncthreads();

        const uint32_t st = sb + (kt % 3) * FB_STAGE;
        #pragma unroll
        for (int hh = 0; hh < 2; hh++) {
            uint32_t ah[4][4], al[4][4], bh[4][2], bl[4][2];
            #pragma unroll
            for (int mi = 0; mi < 4; mi++) {
                uint32_t ra = st + (aRow + mi * 16) * 80 + hh * 32 + aChunk;
                LDSM4(ah[mi], ra);
                LDSM4(al[mi], ra + 10240);
            }
            #pragma unroll
            for (int p = 0; p < 2; p++) {
                uint32_t rb = st + 20480 + (bRow + p * 16) * 80 + hh * 32 + bChunk;
                uint32_t r[4];
                LDSM4(r, rb);
                bh[2*p][0] = r[0]; bh[2*p][1] = r[1];
                bh[2*p+1][0] = r[2]; bh[2*p+1][1] = r[3];
                LDSM4(r, rb + 10240);
                bl[2*p][0] = r[0]; bl[2*p][1] = r[1];
                bl[2*p+1][0] = r[2]; bl[2*p+1][1] = r[3];
            }
            #pragma unroll
            for (int mi = 0; mi < 4; mi++)
                #pragma unroll
                for (int ni = 0; ni < 4; ni++) {
                    MMA16816(acc[mi][ni], ah[mi], bh[ni]);
                    MMA16816(acc[mi][ni], ah[mi], bl[ni]);
                    MMA16816(acc[mi][ni], al[mi], bh[ni]);
                }
        }
        __syncthreads();
    }

    float* sRed = (float*)smem;
    const int tq = lane & 3, rq = lane >> 2;

    if (ntile < 16) {
        #pragma unroll
        for (int mi = 0; mi < 4; mi++) {
            float vs0 = 0.f, vs1 = 0.f;
            const int r0 = m0 + wm * 64 + mi * 16 + rq;
            #pragma unroll
            for (int ni = 0; ni < 4; ni++) {
                const int n = n0 + wn * 32 + ni * 8 + tq * 2;
                float b0 = vb[n], b1 = vb[n + 1];
                float v00 = acc[mi][ni][0] + b0, v01 = acc[mi][ni][1] + b1;
                float v10 = acc[mi][ni][2] + b0, v11 = acc[mi][ni][3] + b1;
                *(float2*)(g_vp + (size_t)r0 * HIDn + n)       = make_float2(v00, v01);
                *(float2*)(g_vp + (size_t)(r0 + 8) * HIDn + n) = make_float2(v10, v11);
                vs0 += v00 * v00 + v01 * v01;
                vs1 += v10 * v10 + v11 * v11;
            }
            vs0 += __shfl_xor_sync(~0u, vs0, 1); vs0 += __shfl_xor_sync(~0u, vs0, 2);
            vs1 += __shfl_xor_sync(~0u, vs1, 1); vs1 += __shfl_xor_sync(~0u, vs1, 2);
            if (tq == 0) {
                int lr = wm * 64 + mi * 16 + rq;
                sRed[wn * 128 + lr]     = vs0;
                sRed[wn * 128 + lr + 8] = vs1;
            }
        }
        __syncthreads();
        if (tid < 128) {
            float s = sRed[tid] + sRed[128 + tid] + sRed[256 + tid] + sRed[384 + tid];
            g_vsq[(m0 + tid) * 16 + ntile] = s;
        }
    } else {
        const int kbase = (ntile - 16) * 128;
        const int hc = (kbase >> 7) & 3;
        const int q  = kbase >> 9;
        float* sPn = sRed;
        float* sPs = sRed + 512;
        #pragma unroll
        for (int mi = 0; mi < 4; mi++) {
            float pn0 = 0.f, ps0 = 0.f, pn1 = 0.f, ps1 = 0.f;
            const int r0 = m0 + wm * 64 + mi * 16 + rq;
            #pragma unroll
            for (int ni = 0; ni < 4; ni++) {
                const int cl = wn * 32 + ni * 8 + tq * 2;
                const int dd = q * 128 + cl;
                const int nb = hc * HIDn + dd;
                float b0 = kb[nb], b1 = kb[nb + 1];
                float w0 = n1[nb] * n2[nb], w1 = n1[nb + 1] * n2[nb + 1];
                float k00 = acc[mi][ni][0] + b0, k01 = acc[mi][ni][1] + b1;
                float k10 = acc[mi][ni][2] + b0, k11 = acc[mi][ni][3] + b1;
                const float* h0 = hid + (size_t)r0 * HIDn + dd;
                const float* h1 = hid + (size_t)(r0 + 8) * HIDn + dd;
                pn0 += k00 * w0 * h0[0] + k01 * w1 * h0[1];
                ps0 += k00 * k00 + k01 * k01;
                pn1 += k10 * w0 * h1[0] + k11 * w1 * h1[1];
                ps1 += k10 * k10 + k11 * k11;
            }
            pn0 += __shfl_xor_sync(~0u, pn0, 1); pn0 += __shfl_xor_sync(~0u, pn0, 2);
            ps0 += __shfl_xor_sync(~0u, ps0, 1); ps0 += __shfl_xor_sync(~0u, ps0, 2);
            pn1 += __shfl_xor_sync(~0u, pn1, 1); pn1 += __shfl_xor_sync(~0u, pn1, 2);
            ps1 += __shfl_xor_sync(~0u, ps1, 1); ps1 += __shfl_xor_sync(~0u, ps1, 2);
            if (tq == 0) {
                int lr = wm * 64 + mi * 16 + rq;
                sPn[wn * 128 + lr]     = pn0;  sPn[wn * 128 + lr + 8] = pn1;
                sPs[wn * 128 + lr]     = ps0;  sPs[wn * 128 + lr + 8] = ps1;
            }
        }
        __syncthreads();
        if (tid < 128) {
            float pn = sPn[tid] + sPn[128 + tid] + sPn[256 + tid] + sPn[384 + tid];
            float ps = sPs[tid] + sPs[128 + tid] + sPs[256 + tid] + sPs[384 + tid];
            g_pnum[((size_t)(m0 + tid) * HCn + hc) * 16 + q] = pn;
            g_psq [((size_t)(m0 + tid) * HCn + hc) * 16 + q] = ps;
        }
    }
#endif
}

// ---------------- K4: gates, alpha, sgate (one warp per row) ----------------
__global__ void k_gate()
{
    const int row  = blockIdx.x;
    const int lane = threadIdx.x;

    float v = (lane < 16) ? g_vsq[row * 16 + lane] : 0.f;
    #pragma unroll
    for (int q = 16; q > 0; q >>= 1) v += __shfl_down_sync(0xffffffffu, v, q);
    const float smsq = __shfl_sync(0xffffffffu, v, 0) * (1.f / HIDn);

    const int g = lane >> 3, j = lane & 7;
    const float* pn = g_pnum + ((size_t)row * HCn + g) * 16;
    const float* pq = g_psq  + ((size_t)row * HCn + g) * 16;
    float num = pn[j] + pn[j + 8];
    float sq  = pq[j] + pq[j + 8];
    #pragma unroll
    for (int q = 4; q > 0; q >>= 1) {
        num += __shfl_down_sync(0xffffffffu, num, q, 8);
        sq  += __shfl_down_sync(0xffffffffu, sq,  q, 8);
    }
    float gate = 0.f;
    if (j == 0) {
        float irk = rsqrtf(sq * (1.f / HIDn) + EPS_RMS);
        float gg  = num * irk * g_invq[row] * 0.022097086912079608f;   // 1/sqrt(2048)
        float sgn = (gg > 0.f) ? 1.f : ((gg < 0.f) ? -1.f : 0.f);
        float gs  = sgn * sqrtf(fmaxf(fabsf(gg), 1e-6f));
        gate = 1.f / (1.f + __expf(-gs));
        g_alpha[(size_t)row * HCn + g] = gate * rsqrtf(gate * gate * smsq + EPS_SC);
    }
    float sg = __shfl_sync(0xffffffffu, gate, 0) + __shfl_sync(0xffffffffu, gate, 8)
             + __shfl_sync(0xffffffffu, gate, 16) + __shfl_sync(0xffffffffu, gate, 24);
    if (lane == 0) g_sgate[row] = sg;
}

// ---------------- K5: TILED dilated depthwise conv + silu + hc-sum ----------
// block = (128 ch x 64 t); vp window staged once in SMEM (73 rows), cutting
// global vp reads ~3.5x vs the old per-output 4-tap gather.
__global__ void __launch_bounds__(256)
k_out(const float* __restrict__ scw,
      const float* __restrict__ cw,
      float* __restrict__ out)
{
    __shared__ float sv[73][128];
    __shared__ float sal[73][4];
    __shared__ float ssg[64];

    const int c0 = blockIdx.x * 128;
    const int t0 = blockIdx.y * 64;
    const int b  = blockIdx.z;
    const int tid = threadIdx.x;
    const int rbase = b * Ln;

    // stage vp window (73 rows x 128 ch), zero rows for t<0
    for (int i = tid; i < 73 * 32; i += 256) {
        int rr = i >> 5, q = i & 31;
        int t = t0 - 9 + rr;
        float4 v = make_float4(0.f, 0.f, 0.f, 0.f);
        if (t >= 0)
            v = *(const float4*)(g_vp + (size_t)(rbase + t) * HIDn + c0 + q * 4);
        *(float4*)&sv[rr][q * 4] = v;
    }
    // stage alpha window
    for (int i = tid; i < 73; i += 256) {
        int t = t0 - 9 + i;
        float4 a = make_float4(0.f, 0.f, 0.f, 0.f);
        if (t >= 0) a = *(const float4*)(g_alpha + (size_t)(rbase + t) * HCn);
        *(float4*)&sal[i][0] = a;
    }
    if (tid < 64) ssg[tid] = g_sgate[rbase + t0 + tid];
    __syncthreads();

    const int c4 = tid & 31;        // channel quad within the 128-ch tile
    const int tr = tid >> 5;        // warp id: t-subrange
    const int c  = c0 + c4 * 4;

    // per-thread weights: w[g][j] = 4 taps for channel c+j, group g
    float4 wreg[4][4];
    float  screg[4][4];
    #pragma unroll
    for (int g = 0; g < 4; g++)
        #pragma unroll
        for (int j = 0; j < 4; j++) {
            wreg[g][j]  = *(const float4*)(cw + ((size_t)(g * HIDn + c + j)) * 4);
            screg[g][j] = scw[g * HIDn + c + j];
        }

    #pragma unroll
    for (int jt = 0; jt < 8; jt++) {
        const int tl = tr * 8 + jt;          // 0..63
        float vk[4][4];                      // [tap][channel]
        float alk[4][4];                     // [tap][g]
        #pragma unroll
        for (int k = 0; k < 4; k++) {
            float4 v = *(const float4*)&sv[tl + 3 * k][c4 * 4];
            vk[k][0] = v.x; vk[k][1] = v.y; vk[k][2] = v.z; vk[k][3] = v.w;
            #pragma unroll
            for (int g = 0; g < 4; g++) alk[k][g] = sal[tl + 3 * k][g];
        }
        const float sg = ssg[tl];
        float o[4] = { sg * vk[3][0], sg * vk[3][1], sg * vk[3][2], sg * vk[3][3] };
        #pragma unroll
        for (int g = 0; g < 4; g++) {
            #pragma unroll
            for (int j = 0; j < 4; j++) {
                const float4 w = wreg[g][j];
                float y = w.x * alk[0][g] * vk[0][j]
                        + w.y * alk[1][g] * vk[1][j]
                        + w.z * alk[2][g] * vk[2][j]
                        + w.w * alk[3][g] * vk[3][j];
                y *= screg[g][j];
                o[j] += y / (1.f + __expf(-y));
            }
        }
        *(float4*)(out + (size_t)(rbase + t0 + tl) * HIDn + c) =
            make_float4(o[0], o[1], o[2], o[3]);
    }
}

// ---------------- host: tensormap construction + launch ----------------
typedef CUresult (*PFN_tmEncode)(
    CUtensorMap*, CUtensorMapDataType, cuuint32_t, void*,
    const cuuint64_t*, const cuuint64_t*, const cuuint32_t*, const cuuint32_t*,
    CUtensorMapInterleave, CUtensorMapSwizzle, CUtensorMapL2promotion,
    CUtensorMapFloatOOBfill);

static void encode_map(PFN_tmEncode fn, CUtensorMap* tm, void* base, unsigned rows)
{
    cuuint64_t dims[2]    = {2048ull, (cuuint64_t)rows};  // bytes per row, rows
    cuuint64_t strides[1] = {2048ull};
    cuuint32_t box[2]     = {128u, 128u};
    cuuint32_t es[2]      = {1u, 1u};
    fn(tm, CU_TENSOR_MAP_DATA_TYPE_UINT8, 2, base, dims, strides, box, es,
       CU_TENSOR_MAP_INTERLEAVE_NONE, CU_TENSOR_MAP_SWIZZLE_128B,
       CU_TENSOR_MAP_L2_PROMOTION_L2_128B, CU_TENSOR_MAP_FLOAT_OOB_FILL_NONE);
}

extern "C" void kernel_launch(void* const* d_in, const int* in_sizes, int n_in,
                              void* d_out, int out_size)
{
    (void)in_sizes; (void)n_in; (void)out_size;
    const float* hid = (const float*)d_in[0];
    const void*  ids = d_in[1];
    const float* tab = (const float*)d_in[2];
    const float* vw  = (const float*)d_in[3];
    const float* vb  = (const float*)d_in[4];
    const float* kw  = (const float*)d_in[5];
    const float* kb  = (const float*)d_in[6];
    const float* n1  = (const float*)d_in[7];
    const float* n2  = (const float*)d_in[8];
    const float* scw = (const float*)d_in[9];
    const float* cw  = (const float*)d_in[10];
    float* out = (float*)d_out;

    PFN_tmEncode fn = nullptr;
    cudaDriverEntryPointQueryResult qres;
    cudaGetDriverEntryPointByVersion("cuTensorMapEncodeTiled", (void**)&fn,
                                     12000, cudaEnableDefault, &qres);
    void *pAh, *pAl, *pBh, *pBl;
    cudaGetSymbolAddress(&pAh, g_embh);
    cudaGetSymbolAddress(&pAl, g_embl);
    cudaGetSymbolAddress(&pBh, g_wth);
    cudaGetSymbolAddress(&pBl, g_wtl);
    CUtensorMap tmAh{}, tmAl{}, tmBh{}, tmBl{};
    if (fn) {
        encode_map(fn, &tmAh, pAh, Mn);
        encode_map(fn, &tmAl, pAl, Mn);
        encode_map(fn, &tmBh, pBh, NTOT);
        encode_map(fn, &tmBl, pBl, NTOT);
    }

    cudaFuncSetAttribute(k_tcgemm,  cudaFuncAttributeMaxDynamicSharedMemorySize, GSMEM);
    cudaFuncSetAttribute(k_gemm_fb, cudaFuncAttributeMaxDynamicSharedMemorySize, FB_SMEM);

    k_gather<<<Mn, 256>>>(ids, tab, hid);
    k_wt<<<dim3(NTOT / 64, ENGn / 64), 256>>>(vw, kw);
    k_gemm_fb<<<dim3(80, 64), 256, FB_SMEM>>>(vb, kb, n1, n2, hid);   // active iff no sm_103a
    k_tcgemm<<<dim3(64, 20), 256, GSMEM>>>(tmAh, tmAl, tmBh, tmBl,
                                           vb, kb, n1, n2, hid);      // 4th launch -> profiled
    k_gate<<<Mn, 32>>>();
    k_out<<<dim3(HIDn / 128, Ln / 64, Bn), 256>>>(scw, cw, out);
}

// round 13
// speedup vs baseline: 1.1582x; 1.1582x over previous
#include <cuda_runtime.h>
#include <cuda.h>
#include <cuda_bf16.h>
#include <cstdint>

#define Bn 2
#define Ln 4096
#define Mn (Bn*Ln)          // 8192 rows
#define HIDn 2048
#define ENGn 1024
#define NHEADn 16
#define VOCABn 129280
#define HCn 4
#define NTOT 10240          // 2048 value cols + 4*2048 key cols
#define EPS_RMS 1.1920929e-07f
#define EPS_SC  1e-5f

#if defined(__CUDA_ARCH__) && (__CUDA_ARCH__ == 1030) && defined(__CUDA_ARCH_FEAT_SM103_ALL)
#define USE_TC 1
#else
#define USE_TC 0
#endif

// ---------------- scratch (device globals: allocation-free) ----------------
__device__ __nv_bfloat16 g_embh[(size_t)Mn * ENGn];
__device__ __nv_bfloat16 g_embl[(size_t)Mn * ENGn];
__device__ __nv_bfloat16 g_wth [(size_t)NTOT * ENGn];  // W^T hi (keys hc-interleaved)
__device__ __nv_bfloat16 g_wtl [(size_t)NTOT * ENGn];  // W^T lo (key rows stay zero)
__device__ float g_vp [(size_t)Mn * HIDn];
__device__ float g_invq[Mn];
__device__ float g_vsq [Mn * 16];
__device__ float g_pnum[Mn * HCn * 16];
__device__ float g_psq [Mn * HCn * 16];
__device__ float g_alpha[Mn * HCn];
__device__ float g_sgate[Mn];

__device__ __forceinline__ uint32_t sm2u(const void* p) {
    return (uint32_t)__cvta_generic_to_shared(p);
}

// ---------------- K1: gather -> bf16 hi/lo + hidden row rms ----------------
__global__ void k_gather(const void* __restrict__ ids_raw,
                         const float* __restrict__ tab,
                         const float* __restrict__ hid)
{
    const int row = blockIdx.x;
    const int tid = threadIdx.x;
    __shared__ int   sid[NHEADn];
    __shared__ float sbuf[32];

    if (tid == 0) {
        const long long* p64 = (const long long*)ids_raw;
        bool is64 = true;
        #pragma unroll
        for (int i = 0; i < 8; i++) {
            long long v = p64[i];
            if (v < 0 || v >= (long long)VOCABn) { is64 = false; break; }
        }
        if (is64) {
            const long long* p = p64 + (size_t)row * NHEADn;
            for (int h = 0; h < NHEADn; h++) sid[h] = (int)p[h];
        } else {
            const int* p = ((const int*)ids_raw) + (size_t)row * NHEADn;
            for (int h = 0; h < NHEADn; h++) sid[h] = p[h];
        }
    }
    __syncthreads();

    #pragma unroll
    for (int e = tid; e < ENGn; e += 256) {
        int h = e >> 6, d = e & 63;
        float v = tab[((size_t)h * VOCABn + (size_t)sid[h]) * 64 + d];
        __nv_bfloat16 hi = __float2bfloat16(v);
        __nv_bfloat16 lo = __float2bfloat16(v - __bfloat162float(hi));
        g_embh[(size_t)row * ENGn + e] = hi;
        g_embl[(size_t)row * ENGn + e] = lo;
    }

    float s = 0.f;
    const float* hr = hid + (size_t)row * HIDn;
    for (int i = tid; i < HIDn; i += 256) { float v = hr[i]; s += v * v; }
    {
        int lane = tid & 31, wid = tid >> 5;
        #pragma unroll
        for (int q = 16; q > 0; q >>= 1) s += __shfl_down_sync(0xffffffffu, s, q);
        if (lane == 0) sbuf[wid] = s;
        __syncthreads();
        if (wid == 0) {
            s = (lane < 8) ? sbuf[lane] : 0.f;
            #pragma unroll
            for (int q = 4; q > 0; q >>= 1) s += __shfl_down_sync(0xffffffffu, s, q);
            if (lane == 0) g_invq[row] = rsqrtf(s * (1.f / HIDn) + EPS_RMS);
        }
    }
}

// ---------------- K2: weight transpose + bf16 hi/lo split ----------------
// value rows: hi+lo. key rows (hc-interleaved n' = 2048 + (d>>7)*512 + hc*128
// + (d&127)): hi ONLY — keys GEMM is pure bf16.
__global__ void k_wt(const float* __restrict__ vw, const float* __restrict__ kw)
{
    __shared__ float ts[64][65];
    const int n0 = blockIdx.x * 64;
    const int k0 = blockIdx.y * 64;
    const int s  = n0 >> 11;
    const float* W = (s == 0) ? vw : kw + (size_t)(s - 1) * ENGn * HIDn;
    const int col0 = n0 & 2047;
    const int tx  = threadIdx.x & 63;
    const int ty4 = threadIdx.x >> 6;

    #pragma unroll
    for (int i = 0; i < 16; i++) {
        int kk = ty4 + i * 4;
        ts[kk][tx] = W[(size_t)(k0 + kk) * HIDn + col0 + tx];
    }
    __syncthreads();
    #pragma unroll
    for (int i = 0; i < 16; i++) {
        int nn = ty4 + i * 4;
        float v = ts[tx][nn];
        __nv_bfloat16 hi = __float2bfloat16(v);
        if (s == 0) {
            int orow = n0 + nn;
            size_t o = (size_t)orow * ENGn + k0 + tx;
            g_wth[o] = hi;
            g_wtl[o] = __float2bfloat16(v - __bfloat162float(hi));
        } else {
            int d = col0 + nn;
            int orow = 2048 + ((d >> 7) << 9) + ((s - 1) << 7) + (d & 127);
            g_wth[(size_t)orow * ENGn + k0 + tx] = hi;   // lo stays zero
        }
    }
}

// ================= tcgen05 path (sm_103a feature target) =====================
// cluster pair computes D[256 M, 512 N] over K=1024; 16 kchunks of 64.
// value tiles (nsup<4): 3-term bf16x3 (96KB/chunk, 24 MMAs).
// key tiles: PURE bf16 (AhBh only): 48KB/chunk, 8 MMAs, no fullB barrier.
#define STAGE_B 98304
#define GSMEM   (1024 + 2 * STAGE_B)

#if USE_TC
__device__ __forceinline__ uint64_t mk_desc(uint32_t addr) {
    // SW128, Blackwell version=1, LBO=1, SBO=64 (K-major, 128B rows)
    return 0x4000404000010000ull | (uint64_t)((addr >> 4) & 0x3FFF);
}
__device__ __forceinline__ void mbar_wait(uint32_t a, int ph) {
    asm volatile(
        "{\n\t.reg .pred P;\n\t"
        "W_%=:\n\t"
        "mbarrier.try_wait.parity.acquire.cluster.shared::cta.b64 P, [%0], %1, 0x989680;\n\t"
        "@P bra.uni D_%=;\n\t"
        "bra.uni W_%=;\n\t"
        "D_%=:\n\t}"
        :: "r"(a), "r"(ph) : "memory");
}
__device__ __forceinline__ void remote_arrive(uint32_t a) {
    uint32_t zero = 0;
    asm volatile(
        "{\n\t.reg .b32 ra;\n\t"
        "mapa.shared::cluster.u32 ra, %0, %1;\n\t"
        "mbarrier.arrive.shared::cluster.b64 _, [ra];\n\t}"
        :: "r"(a), "r"(zero) : "memory");
}
__device__ __forceinline__ void mma_f16_cg2(uint32_t d, uint64_t da, uint64_t db,
                                            uint32_t idesc, bool en) {
    uint32_t e = en ? 1u : 0u, z = 0u;
    asm volatile(
        "{\n\t.reg .pred p;\n\t"
        "setp.ne.u32 p, %5, 0;\n\t"
        "tcgen05.mma.cta_group::2.kind::f16 [%0], %1, %2, %3, "
        "{%4, %4, %4, %4, %4, %4, %4, %4}, p;\n\t}"
        :: "r"(d), "l"(da), "l"(db), "r"(idesc), "r"(z), "r"(e) : "memory");
}
#define TC_LD32(r, a) \
    asm volatile("tcgen05.ld.sync.aligned.32x32b.x32.b32 " \
        "{%0, %1, %2, %3, %4, %5, %6, %7, %8, %9, %10, %11, %12, %13, %14, %15, " \
        "%16, %17, %18, %19, %20, %21, %22, %23, %24, %25, %26, %27, %28, %29, %30, %31}, [%32];" \
        : "=r"((r)[0]), "=r"((r)[1]), "=r"((r)[2]), "=r"((r)[3]), \
          "=r"((r)[4]), "=r"((r)[5]), "=r"((r)[6]), "=r"((r)[7]), \
          "=r"((r)[8]), "=r"((r)[9]), "=r"((r)[10]), "=r"((r)[11]), \
          "=r"((r)[12]), "=r"((r)[13]), "=r"((r)[14]), "=r"((r)[15]), \
          "=r"((r)[16]), "=r"((r)[17]), "=r"((r)[18]), "=r"((r)[19]), \
          "=r"((r)[20]), "=r"((r)[21]), "=r"((r)[22]), "=r"((r)[23]), \
          "=r"((r)[24]), "=r"((r)[25]), "=r"((r)[26]), "=r"((r)[27]), \
          "=r"((r)[28]), "=r"((r)[29]), "=r"((r)[30]), "=r"((r)[31]) \
        : "r"(a))
#define TC_WAIT_LD() asm volatile("tcgen05.wait::ld.sync.aligned;" ::: "memory")
#define TMA2D(dst, map, x, y, bar) \
    asm volatile("cp.async.bulk.tensor.2d.shared::cta.global.tile" \
                 ".mbarrier::complete_tx::bytes [%0], [%1, {%2, %3}], [%4];" \
                 :: "r"(dst), "l"(map), "r"(x), "r"(y), "r"(bar) : "memory")
#define MBAR_EXPECT(bar, bytes) \
    asm volatile("mbarrier.arrive.expect_tx.shared.b64 _, [%0], %1;" \
                 :: "r"(bar), "r"(bytes) : "memory")
#endif

__global__ void __launch_bounds__(256, 1) __cluster_dims__(2, 1, 1)
k_tcgemm(const __grid_constant__ CUtensorMap tmAh,
         const __grid_constant__ CUtensorMap tmAl,
         const __grid_constant__ CUtensorMap tmBh,
         const __grid_constant__ CUtensorMap tmBl,
         const float* __restrict__ vb, const float* __restrict__ kb,
         const float* __restrict__ n1, const float* __restrict__ n2,
         const float* __restrict__ hid)
{
#if !USE_TC
    (void)vb; (void)kb; (void)n1; (void)n2; (void)hid;
    return;
#else
    extern __shared__ char sm[];
    const int tid  = threadIdx.x;
    const int rank = blockIdx.x & 1;
    const int m0   = (blockIdx.x >> 1) * 256;
    const int nsup = blockIdx.y;                       // 0..19
    const bool isKey = (nsup >= 4);
    const uint32_t sb = sm2u(sm);
    // barriers: fullA[2]@16, fullB[2]@32, relA[2]@48, relB[2]@64, done[2]@80
    const uint32_t mb_fullA = sb + 16;
    const uint32_t mb_fullB = sb + 32;
    const uint32_t mb_relA  = sb + 48;
    const uint32_t mb_relB  = sb + 64;
    const uint32_t mb_done  = sb + 80;

    if (tid == 0) {
        #pragma unroll
        for (int s = 0; s < 2; s++) {
            asm volatile("mbarrier.init.shared.b64 [%0], 1;" :: "r"(mb_fullA + s * 8) : "memory");
            asm volatile("mbarrier.init.shared.b64 [%0], 1;" :: "r"(mb_fullB + s * 8) : "memory");
            asm volatile("mbarrier.init.shared.b64 [%0], 1;" :: "r"(mb_relA  + s * 8) : "memory");
            asm volatile("mbarrier.init.shared.b64 [%0], 1;" :: "r"(mb_relB  + s * 8) : "memory");
            asm volatile("mbarrier.init.shared.b64 [%0], 1;" :: "r"(mb_done  + s * 8) : "memory");
        }
    }
    if (tid < 32) {
        asm volatile("tcgen05.alloc.cta_group::2.sync.aligned.shared::cta.b32 [%0], 512;"
                     :: "r"(sb) : "memory");
    }
    __syncthreads();
    uint32_t tmem;
    asm volatile("ld.shared.b32 %0, [%1];" : "=r"(tmem) : "r"(sb));
    asm volatile("barrier.cluster.arrive.aligned;" ::: "memory");
    asm volatile("barrier.cluster.wait.aligned;"   ::: "memory");

    const uint32_t idesc = (1u << 4) | (1u << 7) | (1u << 10)
                         | ((256u / 8) << 17) | ((256u / 16) << 24);

    if (tid == 0) {
        const int ar  = m0 + rank * 128;                // A row base
        const int br0 = nsup * 512 + rank * 128;        // B rows half 0
        const int br1 = nsup * 512 + 256 + rank * 128;  // B rows half 1
        int fphA[2] = {0,0}, fphB[2] = {0,0};
        int rphA[2] = {0,0}, rphB[2] = {0,0};
        int dph [2] = {0,0};

        auto issue = [&](int kc, int s) {
            const uint32_t d0 = sb + 1024 + s * STAGE_B;
            const int x = kc * 128;
            // A-half: Ah + Bh (48KB) -> fullA
            MBAR_EXPECT(mb_fullA + s * 8, 49152u);
            TMA2D(d0,          &tmAh, x, ar,  mb_fullA + s * 8);
            TMA2D(d0 + 32768,  &tmBh, x, br0, mb_fullA + s * 8);
            TMA2D(d0 + 49152,  &tmBh, x, br1, mb_fullA + s * 8);
            // B-half (value tiles only): Al + Bl -> fullB
            if (!isKey) {
                MBAR_EXPECT(mb_fullB + s * 8, 49152u);
                TMA2D(d0 + 16384,  &tmAl, x, ar,  mb_fullB + s * 8);
                TMA2D(d0 + 65536,  &tmBl, x, br0, mb_fullB + s * 8);
                TMA2D(d0 + 81920,  &tmBl, x, br1, mb_fullB + s * 8);
            }
        };
        auto compute = [&](int kc, int sp) {
            if (rank == 0) {
                mbar_wait(mb_fullA + sp * 8, fphA[sp]); fphA[sp] ^= 1;
                mbar_wait(mb_relA  + sp * 8, rphA[sp]); rphA[sp] ^= 1;
                const uint32_t a = sb + 1024 + sp * STAGE_B;
                const uint64_t dAh = mk_desc(a);
                #pragma unroll
                for (int h = 0; h < 2; h++) {
                    const uint64_t dBh = mk_desc(a + 32768 + h * 16384);
                    const uint32_t dst = tmem + h * 256;
                    #pragma unroll
                    for (int ks = 0; ks < 4; ks++)
                        mma_f16_cg2(dst, dAh + ks * 2, dBh + ks * 2, idesc,
                                    !(kc == 0 && ks == 0));
                }
                if (!isKey) {
                    mbar_wait(mb_fullB + sp * 8, fphB[sp]); fphB[sp] ^= 1;
                    mbar_wait(mb_relB  + sp * 8, rphB[sp]); rphB[sp] ^= 1;
                    const uint64_t dAl = mk_desc(a + 16384);
                    #pragma unroll
                    for (int h = 0; h < 2; h++) {
                        const uint64_t dBh = mk_desc(a + 32768 + h * 16384);
                        const uint64_t dBl = mk_desc(a + 65536 + h * 16384);
                        const uint32_t dst = tmem + h * 256;
                        #pragma unroll
                        for (int ks = 0; ks < 4; ks++) {
                            mma_f16_cg2(dst, dAh + ks * 2, dBl + ks * 2, idesc, true);
                            mma_f16_cg2(dst, dAl + ks * 2, dBh + ks * 2, idesc, true);
                        }
                    }
                }
                asm volatile(
                    "tcgen05.commit.cta_group::2.mbarrier::arrive::one.shared::cluster"
                    ".multicast::cluster.b64 [%0], %1;"
                    :: "r"(mb_done + sp * 8), "h"((uint16_t)3) : "memory");
            } else {
                mbar_wait(mb_fullA + sp * 8, fphA[sp]); fphA[sp] ^= 1;
                remote_arrive(mb_relA + sp * 8);
                if (!isKey) {
                    mbar_wait(mb_fullB + sp * 8, fphB[sp]); fphB[sp] ^= 1;
                    remote_arrive(mb_relB + sp * 8);
                }
            }
        };

        #pragma unroll 1
        for (int kc = 0; kc < 16; kc++) {
            const int s = kc & 1;
            if (kc >= 2) { mbar_wait(mb_done + s * 8, dph[s]); dph[s] ^= 1; }
            issue(kc, s);
            if (kc >= 1) compute(kc - 1, s ^ 1);
        }
        compute(15, 1);
        mbar_wait(mb_done + 8, dph[1]);   // all 16 chunks' MMAs retired
    }
    __syncthreads();
    asm volatile("tcgen05.fence::after_thread_sync;" ::: "memory");

    // -------- coalesced epilogue (per-warp 32x33 SMEM transpose tile) --------
    const int w = tid >> 5, lane = tid & 31;
    const int h  = w >> 2;                      // col half (0: 0-255, 1: 256-511)
    const int rg = w & 3;                       // row group within CTA
    const int r0 = m0 + rank * 128 + rg * 32;
    const int r  = r0 + lane;
    float* tile = (float*)(sm + 1024) + w * (32 * 33);

    if (nsup < 4) {
        // ---- value projection: vp = D + vb, accumulate sum(vp^2) ----
        float vsq = 0.f;
        const int nb0 = nsup * 512 + h * 256;
        #pragma unroll
        for (int q = 0; q < 8; q++) {
            uint32_t d[32];
            TC_LD32(d, tmem + h * 256 + q * 32);
            TC_WAIT_LD();
            const int nb = nb0 + q * 32;
            #pragma unroll
            for (int c = 0; c < 32; c++) {
                float o = __uint_as_float(d[c]) + __ldg(vb + nb + c);
                vsq = fmaf(o, o, vsq);
                tile[lane * 33 + c] = o;
            }
            __syncwarp();
            #pragma unroll
            for (int rr = 0; rr < 32; rr++)
                g_vp[(size_t)(r0 + rr) * HIDn + nb + lane] = tile[rr * 33 + lane];
            __syncwarp();
        }
        g_vsq[r * 16 + nsup * 2 + h] = vsq;
    } else {
        // ---- keys (hc-interleaved): reduce to gate partials ----
        const int q = nsup - 4;                  // 0..15 d-chunk
        float pn[2] = {0.f, 0.f}, ps[2] = {0.f, 0.f};
        #pragma unroll
        for (int dq = 0; dq < 4; dq++) {
            const int dwin = q * 128 + dq * 32;
            #pragma unroll
            for (int rr = 0; rr < 32; rr++)      // coalesced hid stage
                tile[rr * 33 + lane] = __ldg(hid + (size_t)(r0 + rr) * HIDn + dwin + lane);
            __syncwarp();
            #pragma unroll
            for (int hcl = 0; hcl < 2; hcl++) {
                const int hc = h * 2 + hcl;
                uint32_t d[32];
                TC_LD32(d, tmem + h * 256 + hcl * 128 + dq * 32);
                TC_WAIT_LD();
                const int nb = hc * HIDn + dwin;
                #pragma unroll
                for (int c = 0; c < 32; c++) {
                    float kv = __uint_as_float(d[c]) + __ldg(kb + nb + c);
                    float w12 = __ldg(n1 + nb + c) * __ldg(n2 + nb + c);
                    pn[hcl] = fmaf(kv * w12, tile[lane * 33 + c], pn[hcl]);
                    ps[hcl] = fmaf(kv, kv, ps[hcl]);
                }
            }
            __syncwarp();
        }
        #pragma unroll
        for (int hcl = 0; hcl < 2; hcl++) {
            const int hc = h * 2 + hcl;
            g_pnum[((size_t)r * HCn + hc) * 16 + q] = pn[hcl];
            g_psq [((size_t)r * HCn + hc) * 16 + q] = ps[hcl];
        }
    }

    __syncthreads();
    if (tid < 32) {
        asm volatile("tcgen05.relinquish_alloc_permit.cta_group::2.sync.aligned;");
        asm volatile("tcgen05.dealloc.cta_group::2.sync.aligned.b32 %0, 512;" :: "r"(tmem));
    }
    asm volatile("barrier.cluster.arrive.aligned;" ::: "memory");
    asm volatile("barrier.cluster.wait.aligned;"   ::: "memory");
#endif
}

// ============ fallback: mma.sync bf16x3 pipelined GEMM (plain sm_103) ========
// (dead on sm_103a; launch is skipped host-side when device cc == 10.3)
#define FB_STAGE 40960
#define FB_SMEM  (3 * FB_STAGE)

#define LDSM4(r, addr) \
    asm volatile("ldmatrix.sync.aligned.m8n8.x4.shared.b16 {%0,%1,%2,%3}, [%4];" \
        : "=r"((r)[0]), "=r"((r)[1]), "=r"((r)[2]), "=r"((r)[3]) : "r"(addr))

#define MMA16816(c, a, b) \
    asm volatile("mma.sync.aligned.m16n8k16.row.col.f32.bf16.bf16.f32 " \
        "{%0,%1,%2,%3}, {%4,%5,%6,%7}, {%8,%9}, {%0,%1,%2,%3};" \
        : "+f"((c)[0]), "+f"((c)[1]), "+f"((c)[2]), "+f"((c)[3]) \
        : "r"((a)[0]), "r"((a)[1]), "r"((a)[2]), "r"((a)[3]), \
          "r"((b)[0]), "r"((b)[1]))

__global__ void __launch_bounds__(256, 1)
k_gemm_fb(const float* __restrict__ vb, const float* __restrict__ kb,
          const float* __restrict__ n1, const float* __restrict__ n2,
          const float* __restrict__ hid)
{
#if USE_TC
    (void)vb; (void)kb; (void)n1; (void)n2; (void)hid;
    return;
#else
    extern __shared__ char smem[];
    const uint32_t sb = sm2u(smem);
    const int tid = threadIdx.x;
    const int ntile = blockIdx.x;
    const int m0 = blockIdx.y * 128;
    const int n0 = ntile * 128;

    const char* gA_h = (const char*)(g_embh + (size_t)m0 * ENGn);
    const char* gA_l = (const char*)(g_embl + (size_t)m0 * ENGn);
    const char* gB_h = (const char*)(g_wth + (size_t)n0 * ENGn);
    const char* gB_l = (const char*)(g_wtl + (size_t)n0 * ENGn);

    const int ch = tid & 3;
    auto load_stage = [&](int s, int kc) {
        #pragma unroll
        for (int i = 0; i < 8; i++) {
            const int tsel = i >> 1;
            const int row = (((i & 1) << 8) + tid) >> 2;
            const char* src = (tsel == 0 ? gA_h : tsel == 1 ? gA_l :
                               tsel == 2 ? gB_h : gB_l)
                              + (size_t)row * 2048 + kc * 64 + ch * 16;
            uint32_t d = sb + s * FB_STAGE + tsel * 10240 + row * 80 + ch * 16;
            asm volatile("cp.async.cg.shared.global [%0], [%1], 16;"
                         :: "r"(d), "l"(src));
        }
        asm volatile("cp.async.commit_group;" ::: "memory");
    };

    load_stage(0, 0);
    load_stage(1, 1);

    float acc[4][4][4];
    #pragma unroll
    for (int i = 0; i < 4; i++)
        #pragma unroll
        for (int j = 0; j < 4; j++)
            #pragma unroll
            for (int q = 0; q < 4; q++) acc[i][j][q] = 0.f;

    const int lane = tid & 31, w = tid >> 5;
    const int wm = w >> 2, wn = w & 3;
    const uint32_t aRow   = wm * 64 + (lane & 15);
    const uint32_t aChunk = (lane >> 4) * 16;
    const int g = lane >> 3;
    const uint32_t bRow   = wn * 32 + ((g >> 1) & 1) * 8 + (lane & 7);
    const uint32_t bChunk = (g & 1) * 16;

    for (int kt = 0; kt < 32; kt++) {
        if (kt + 2 < 32) load_stage((kt + 2) % 3, kt + 2);
        else asm volatile("cp.async.commit_group;" ::: "memory");
        asm volatile("cp.async.wait_group 2;" ::: "memory");
        __syncthreads();

        const uint32_t st = sb + (kt % 3) * FB_STAGE;
        #pragma unroll
        for (int hh = 0; hh < 2; hh++) {
            uint32_t ah[4][4], al[4][4], bh[4][2], bl[4][2];
            #pragma unroll
            for (int mi = 0; mi < 4; mi++) {
                uint32_t ra = st + (aRow + mi * 16) * 80 + hh * 32 + aChunk;
                LDSM4(ah[mi], ra);
                LDSM4(al[mi], ra + 10240);
            }
            #pragma unroll
            for (int p = 0; p < 2; p++) {
                uint32_t rb = st + 20480 + (bRow + p * 16) * 80 + hh * 32 + bChunk;
                uint32_t r[4];
                LDSM4(r, rb);
                bh[2*p][0] = r[0]; bh[2*p][1] = r[1];
                bh[2*p+1][0] = r[2]; bh[2*p+1][1] = r[3];
                LDSM4(r, rb + 10240);
                bl[2*p][0] = r[0]; bl[2*p][1] = r[1];
                bl[2*p+1][0] = r[2]; bl[2*p+1][1] = r[3];
            }
            #pragma unroll
            for (int mi = 0; mi < 4; mi++)
                #pragma unroll
                for (int ni = 0; ni < 4; ni++) {
                    MMA16816(acc[mi][ni], ah[mi], bh[ni]);
                    MMA16816(acc[mi][ni], ah[mi], bl[ni]);
                    MMA16816(acc[mi][ni], al[mi], bh[ni]);
                }
        }
        __syncthreads();
    }

    float* sRed = (float*)smem;
    const int tq = lane & 3, rq = lane >> 2;

    if (ntile < 16) {
        #pragma unroll
        for (int mi = 0; mi < 4; mi++) {
            float vs0 = 0.f, vs1 = 0.f;
            const int r0 = m0 + wm * 64 + mi * 16 + rq;
            #pragma unroll
            for (int ni = 0; ni < 4; ni++) {
                const int n = n0 + wn * 32 + ni * 8 + tq * 2;
                float b0 = vb[n], b1 = vb[n + 1];
                float v00 = acc[mi][ni][0] + b0, v01 = acc[mi][ni][1] + b1;
                float v10 = acc[mi][ni][2] + b0, v11 = acc[mi][ni][3] + b1;
                *(float2*)(g_vp + (size_t)r0 * HIDn + n)       = make_float2(v00, v01);
                *(float2*)(g_vp + (size_t)(r0 + 8) * HIDn + n) = make_float2(v10, v11);
                vs0 += v00 * v00 + v01 * v01;
                vs1 += v10 * v10 + v11 * v11;
            }
            vs0 += __shfl_xor_sync(~0u, vs0, 1); vs0 += __shfl_xor_sync(~0u, vs0, 2);
            vs1 += __shfl_xor_sync(~0u, vs1, 1); vs1 += __shfl_xor_sync(~0u, vs1, 2);
            if (tq == 0) {
                int lr = wm * 64 + mi * 16 + rq;
                sRed[wn * 128 + lr]     = vs0;
                sRed[wn * 128 + lr + 8] = vs1;
            }
        }
        __syncthreads();
        if (tid < 128) {
            float s = sRed[tid] + sRed[128 + tid] + sRed[256 + tid] + sRed[384 + tid];
            g_vsq[(m0 + tid) * 16 + ntile] = s;
        }
    } else {
        const int kbase = (ntile - 16) * 128;
        const int hc = (kbase >> 7) & 3;
        const int q  = kbase >> 9;
        float* sPn = sRed;
        float* sPs = sRed + 512;
        #pragma unroll
        for (int mi = 0; mi < 4; mi++) {
            float pn0 = 0.f, ps0 = 0.f, pn1 = 0.f, ps1 = 0.f;
            const int r0 = m0 + wm * 64 + mi * 16 + rq;
            #pragma unroll
            for (int ni = 0; ni < 4; ni++) {
                const int cl = wn * 32 + ni * 8 + tq * 2;
                const int dd = q * 128 + cl;
                const int nb = hc * HIDn + dd;
                float b0 = kb[nb], b1 = kb[nb + 1];
                float w0 = n1[nb] * n2[nb], w1 = n1[nb + 1] * n2[nb + 1];
                float k00 = acc[mi][ni][0] + b0, k01 = acc[mi][ni][1] + b1;
                float k10 = acc[mi][ni][2] + b0, k11 = acc[mi][ni][3] + b1;
                const float* h0 = hid + (size_t)r0 * HIDn + dd;
                const float* h1 = hid + (size_t)(r0 + 8) * HIDn + dd;
                pn0 += k00 * w0 * h0[0] + k01 * w1 * h0[1];
                ps0 += k00 * k00 + k01 * k01;
                pn1 += k10 * w0 * h1[0] + k11 * w1 * h1[1];
                ps1 += k10 * k10 + k11 * k11;
            }
            pn0 += __shfl_xor_sync(~0u, pn0, 1); pn0 += __shfl_xor_sync(~0u, pn0, 2);
            ps0 += __shfl_xor_sync(~0u, ps0, 1); ps0 += __shfl_xor_sync(~0u, ps0, 2);
            pn1 += __shfl_xor_sync(~0u, pn1, 1); pn1 += __shfl_xor_sync(~0u, pn1, 2);
            ps1 += __shfl_xor_sync(~0u, ps1, 1); ps1 += __shfl_xor_sync(~0u, ps1, 2);
            if (tq == 0) {
                int lr = wm * 64 + mi * 16 + rq;
                sPn[wn * 128 + lr]     = pn0;  sPn[wn * 128 + lr + 8] = pn1;
                sPs[wn * 128 + lr]     = ps0;  sPs[wn * 128 + lr + 8] = ps1;
            }
        }
        __syncthreads();
        if (tid < 128) {
            float pn = sPn[tid] + sPn[128 + tid] + sPn[256 + tid] + sPn[384 + tid];
            float ps = sPs[tid] + sPs[128 + tid] + sPs[256 + tid] + sPs[384 + tid];
            g_pnum[((size_t)(m0 + tid) * HCn + hc) * 16 + q] = pn;
            g_psq [((size_t)(m0 + tid) * HCn + hc) * 16 + q] = ps;
        }
    }
#endif
}

// ---------------- K4: gates, alpha, sgate (one warp per row) ----------------
__global__ void k_gate()
{
    const int row  = blockIdx.x;
    const int lane = threadIdx.x;

    float v = (lane < 16) ? g_vsq[row * 16 + lane] : 0.f;
    #pragma unroll
    for (int q = 16; q > 0; q >>= 1) v += __shfl_down_sync(0xffffffffu, v, q);
    const float smsq = __shfl_sync(0xffffffffu, v, 0) * (1.f / HIDn);

    const int g = lane >> 3, j = lane & 7;
    const float* pn = g_pnum + ((size_t)row * HCn + g) * 16;
    const float* pq = g_psq  + ((size_t)row * HCn + g) * 16;
    float num = pn[j] + pn[j + 8];
    float sq  = pq[j] + pq[j + 8];
    #pragma unroll
    for (int q = 4; q > 0; q >>= 1) {
        num += __shfl_down_sync(0xffffffffu, num, q, 8);
        sq  += __shfl_down_sync(0xffffffffu, sq,  q, 8);
    }
    float gate = 0.f;
    if (j == 0) {
        float irk = rsqrtf(sq * (1.f / HIDn) + EPS_RMS);
        float gg  = num * irk * g_invq[row] * 0.022097086912079608f;   // 1/sqrt(2048)
        float sgn = (gg > 0.f) ? 1.f : ((gg < 0.f) ? -1.f : 0.f);
        float gs  = sgn * sqrtf(fmaxf(fabsf(gg), 1e-6f));
        gate = 1.f / (1.f + __expf(-gs));
        g_alpha[(size_t)row * HCn + g] = gate * rsqrtf(gate * gate * smsq + EPS_SC);
    }
    float sg = __shfl_sync(0xffffffffu, gate, 0) + __shfl_sync(0xffffffffu, gate, 8)
             + __shfl_sync(0xffffffffu, gate, 16) + __shfl_sync(0xffffffffu, gate, 24);
    if (lane == 0) g_sgate[row] = sg;
}

// ---------------- K5: fused dilated depthwise conv + silu + hc-sum ----------
// (R11 version: vp is L2-resident, so the 4-tap re-reads are L2 hits)
__global__ void k_out(const float* __restrict__ scw,
                      const float* __restrict__ cw,
                      float* __restrict__ out)
{
    const int idx = blockIdx.x * 256 + threadIdx.x;
    if (idx >= Mn * HIDn / 4) return;
    const int row = idx >> 9;
    const int c   = (idx & 511) << 2;
    const int b = row / Ln;
    const int t = row - b * Ln;

    float v[4][4];
    float al[4][4];
    #pragma unroll
    for (int k = 0; k < 4; k++) {
        int tt = t + 3 * k - 9;
        if (tt >= 0) {
            int r2 = b * Ln + tt;
            float4 vv = *(const float4*)(g_vp + (size_t)r2 * HIDn + c);
            v[k][0] = vv.x; v[k][1] = vv.y; v[k][2] = vv.z; v[k][3] = vv.w;
            #pragma unroll
            for (int g = 0; g < 4; g++) al[k][g] = g_alpha[(size_t)r2 * HCn + g];
        } else {
            #pragma unroll
            for (int j = 0; j < 4; j++) { v[k][j] = 0.f; al[k][j] = 0.f; }
        }
    }

    const float sgate = g_sgate[row];
    float o[4];
    #pragma unroll
    for (int j = 0; j < 4; j++) o[j] = sgate * v[3][j];

    #pragma unroll
    for (int g = 0; g < 4; g++) {
        float4 sw = *(const float4*)(scw + g * HIDn + c);
        float swv[4] = {sw.x, sw.y, sw.z, sw.w};
        #pragma unroll
        for (int j = 0; j < 4; j++) {
            const float4 w = *(const float4*)(cw + ((size_t)(g * HIDn + c + j)) * 4);
            float y = w.x * al[0][g] * v[0][j]
                    + w.y * al[1][g] * v[1][j]
                    + w.z * al[2][g] * v[2][j]
                    + w.w * al[3][g] * v[3][j];
            y *= swv[j];
            o[j] += y / (1.f + __expf(-y));
        }
    }
    *(float4*)(out + (size_t)row * HIDn + c) = make_float4(o[0], o[1], o[2], o[3]);
}

// ---------------- host: tensormap construction + launch ----------------
typedef CUresult (*PFN_tmEncode)(
    CUtensorMap*, CUtensorMapDataType, cuuint32_t, void*,
    const cuuint64_t*, const cuuint64_t*, const cuuint32_t*, const cuuint32_t*,
    CUtensorMapInterleave, CUtensorMapSwizzle, CUtensorMapL2promotion,
    CUtensorMapFloatOOBfill);

static void encode_map(PFN_tmEncode fn, CUtensorMap* tm, void* base, unsigned rows)
{
    cuuint64_t dims[2]    = {2048ull, (cuuint64_t)rows};  // bytes per row, rows
    cuuint64_t strides[1] = {2048ull};
    cuuint32_t box[2]     = {128u, 128u};
    cuuint32_t es[2]      = {1u, 1u};
    fn(tm, CU_TENSOR_MAP_DATA_TYPE_UINT8, 2, base, dims, strides, box, es,
       CU_TENSOR_MAP_INTERLEAVE_NONE, CU_TENSOR_MAP_SWIZZLE_128B,
       CU_TENSOR_MAP_L2_PROMOTION_L2_128B, CU_TENSOR_MAP_FLOAT_OOB_FILL_NONE);
}

extern "C" void kernel_launch(void* const* d_in, const int* in_sizes, int n_in,
                              void* d_out, int out_size)
{
    (void)in_sizes; (void)n_in; (void)out_size;
    const float* hid = (const float*)d_in[0];
    const void*  ids = d_in[1];
    const float* tab = (const float*)d_in[2];
    const float* vw  = (const float*)d_in[3];
    const float* vb  = (const float*)d_in[4];
    const float* kw  = (const float*)d_in[5];
    const float* kb  = (const float*)d_in[6];
    const float* n1  = (const float*)d_in[7];
    const float* n2  = (const float*)d_in[8];
    const float* scw = (const float*)d_in[9];
    const float* cw  = (const float*)d_in[10];
    float* out = (float*)d_out;

    PFN_tmEncode fn = nullptr;
    cudaDriverEntryPointQueryResult qres;
    cudaGetDriverEntryPointByVersion("cuTensorMapEncodeTiled", (void**)&fn,
                                     12000, cudaEnableDefault, &qres);
    void *pAh, *pAl, *pBh, *pBl;
    cudaGetSymbolAddress(&pAh, g_embh);
    cudaGetSymbolAddress(&pAl, g_embl);
    cudaGetSymbolAddress(&pBh, g_wth);
    cudaGetSymbolAddress(&pBl, g_wtl);
    CUtensorMap tmAh{}, tmAl{}, tmBh{}, tmBl{};
    if (fn) {
        encode_map(fn, &tmAh, pAh, Mn);
        encode_map(fn, &tmAl, pAl, Mn);
        encode_map(fn, &tmBh, pBh, NTOT);
        encode_map(fn, &tmBl, pBl, NTOT);
    }

    // the tcgen05 path is compiled for (and active on) cc 10.3 devices; the
    // mma.sync fallback only does work elsewhere. Skip its dead launch here.
    int ccM = 0, ccm = 0, dev = 0;
    cudaGetDevice(&dev);
    cudaDeviceGetAttribute(&ccM, cudaDevAttrComputeCapabilityMajor, dev);
    cudaDeviceGetAttribute(&ccm, cudaDevAttrComputeCapabilityMinor, dev);
    const bool isSm103 = (ccM == 10 && ccm == 3);

    cudaFuncSetAttribute(k_tcgemm,  cudaFuncAttributeMaxDynamicSharedMemorySize, GSMEM);
    cudaFuncSetAttribute(k_gemm_fb, cudaFuncAttributeMaxDynamicSharedMemorySize, FB_SMEM);

    k_gather<<<Mn, 256>>>(ids, tab, hid);
    k_wt<<<dim3(NTOT / 64, ENGn / 64), 256>>>(vw, kw);
    if (!isSm103)
        k_gemm_fb<<<dim3(80, 64), 256, FB_SMEM>>>(vb, kb, n1, n2, hid);
    k_tcgemm<<<dim3(64, 20), 256, GSMEM>>>(tmAh, tmAl, tmBh, tmBl,
                                           vb, kb, n1, n2, hid);
    k_gate<<<Mn, 32>>>();
    k_out<<<(Mn * HIDn / 4 + 255) / 256, 256>>>(scw, cw, out);
}

// round 14
// speedup vs baseline: 1.2123x; 1.0467x over previous
#include <cuda_runtime.h>
#include <cuda.h>
#include <cuda_bf16.h>
#include <cstdint>

#define Bn 2
#define Ln 4096
#define Mn (Bn*Ln)          // 8192 rows
#define HIDn 2048
#define ENGn 1024
#define NHEADn 16
#define VOCABn 129280
#define HCn 4
#define NTOT 10240          // 2048 value cols + 4*2048 key cols
#define EPS_RMS 1.1920929e-07f
#define EPS_SC  1e-5f

#if defined(__CUDA_ARCH__) && (__CUDA_ARCH__ == 1030) && defined(__CUDA_ARCH_FEAT_SM103_ALL)
#define USE_TC 1
#else
#define USE_TC 0
#endif

// ---------------- scratch (device globals: allocation-free) ----------------
__device__ __nv_bfloat16 g_embh[(size_t)Mn * ENGn];
__device__ __nv_bfloat16 g_embl[(size_t)Mn * ENGn];
__device__ __nv_bfloat16 g_wth [(size_t)NTOT * ENGn];  // W^T hi (keys hc-interleaved)
__device__ __nv_bfloat16 g_wtl [(size_t)NTOT * ENGn];  // W^T lo (key rows stay zero)
__device__ float g_vp [(size_t)Mn * HIDn];
__device__ float g_invq[Mn];                           // used by non-TC path only
__device__ float g_hsq [Mn * 16];                      // TC path: hid^2 partials
__device__ float g_vsq [Mn * 16];
__device__ float g_pnum[Mn * HCn * 16];
__device__ float g_psq [Mn * HCn * 16];
__device__ float g_alpha[Mn * HCn];
__device__ float g_sgate[Mn];

__device__ __forceinline__ uint32_t sm2u(const void* p) {
    return (uint32_t)__cvta_generic_to_shared(p);
}

// ---------------- K1: fused gather (+rms on non-TC) and weight transpose ----
// blocks [0, Mn): embedding gather -> bf16 hi/lo (+ hid row rms if !USE_TC)
// blocks [Mn, Mn + 160*16): weight transpose + hi/lo split
//   value rows: hi+lo. key rows hc-interleaved n' = 2048+(d>>7)*512+hc*128+(d&127),
//   hi only (keys GEMM is pure bf16).
__global__ void k_prep(const void* __restrict__ ids_raw,
                       const float* __restrict__ tab,
                       const float* __restrict__ hid,
                       const float* __restrict__ vw,
                       const float* __restrict__ kw)
{
    __shared__ float ts[64][65];
    const int tid = threadIdx.x;

    if (blockIdx.x < Mn) {
        // ---------------- gather ----------------
        const int row = blockIdx.x;
        int* sid = (int*)&ts[0][0];

        if (tid == 0) {
            const long long* p64 = (const long long*)ids_raw;
            bool is64 = true;
            #pragma unroll
            for (int i = 0; i < 8; i++) {
                long long v = p64[i];
                if (v < 0 || v >= (long long)VOCABn) { is64 = false; break; }
            }
            if (is64) {
                const long long* p = p64 + (size_t)row * NHEADn;
                for (int h = 0; h < NHEADn; h++) sid[h] = (int)p[h];
            } else {
                const int* p = ((const int*)ids_raw) + (size_t)row * NHEADn;
                for (int h = 0; h < NHEADn; h++) sid[h] = p[h];
            }
        }
        __syncthreads();

        #pragma unroll
        for (int e = tid; e < ENGn; e += 256) {
            int h = e >> 6, d = e & 63;
            float v = tab[((size_t)h * VOCABn + (size_t)sid[h]) * 64 + d];
            __nv_bfloat16 hi = __float2bfloat16(v);
            __nv_bfloat16 lo = __float2bfloat16(v - __bfloat162float(hi));
            g_embh[(size_t)row * ENGn + e] = hi;
            g_embl[(size_t)row * ENGn + e] = lo;
        }

#if !USE_TC
        // non-TC path: fallback GEMM needs g_invq from here
        float* sbuf = (float*)&ts[1][0];
        float s = 0.f;
        const float* hr = hid + (size_t)row * HIDn;
        for (int i = tid; i < HIDn; i += 256) { float v = hr[i]; s += v * v; }
        int lane = tid & 31, wid = tid >> 5;
        #pragma unroll
        for (int q = 16; q > 0; q >>= 1) s += __shfl_down_sync(0xffffffffu, s, q);
        if (lane == 0) sbuf[wid] = s;
        __syncthreads();
        if (wid == 0) {
            s = (lane < 8) ? sbuf[lane] : 0.f;
            #pragma unroll
            for (int q = 4; q > 0; q >>= 1) s += __shfl_down_sync(0xffffffffu, s, q);
            if (lane == 0) g_invq[row] = rsqrtf(s * (1.f / HIDn) + EPS_RMS);
        }
#else
        (void)hid;
#endif
    } else {
        // ---------------- weight transpose ----------------
        const int wb = blockIdx.x - Mn;
        const int n0 = (wb % 160) * 64;
        const int k0 = (wb / 160) * 64;
        const int s  = n0 >> 11;
        const float* W = (s == 0) ? vw : kw + (size_t)(s - 1) * ENGn * HIDn;
        const int col0 = n0 & 2047;
        const int tx  = tid & 63;
        const int ty4 = tid >> 6;

        #pragma unroll
        for (int i = 0; i < 16; i++) {
            int kk = ty4 + i * 4;
            ts[kk][tx] = W[(size_t)(k0 + kk) * HIDn + col0 + tx];
        }
        __syncthreads();
        #pragma unroll
        for (int i = 0; i < 16; i++) {
            int nn = ty4 + i * 4;
            float v = ts[tx][nn];
            __nv_bfloat16 hi = __float2bfloat16(v);
            if (s == 0) {
                int orow = n0 + nn;
                size_t o = (size_t)orow * ENGn + k0 + tx;
                g_wth[o] = hi;
                g_wtl[o] = __float2bfloat16(v - __bfloat162float(hi));
            } else {
                int d = col0 + nn;
                int orow = 2048 + ((d >> 7) << 9) + ((s - 1) << 7) + (d & 127);
                g_wth[(size_t)orow * ENGn + k0 + tx] = hi;   // lo stays zero
            }
        }
    }
}

// ================= tcgen05 path (sm_103a feature target) =====================
// cluster pair computes D[256 M, 512 N] over K=1024; 16 kchunks of 64.
// value tiles (nsup<4): 3-term bf16x3 (96KB/chunk, 24 MMAs).
// key tiles: PURE bf16 (AhBh only): 48KB/chunk, 8 MMAs, no fullB barrier.
#define STAGE_B 98304
#define GSMEM   (1024 + 2 * STAGE_B)

#if USE_TC
__device__ __forceinline__ uint64_t mk_desc(uint32_t addr) {
    // SW128, Blackwell version=1, LBO=1, SBO=64 (K-major, 128B rows)
    return 0x4000404000010000ull | (uint64_t)((addr >> 4) & 0x3FFF);
}
__device__ __forceinline__ void mbar_wait(uint32_t a, int ph) {
    asm volatile(
        "{\n\t.reg .pred P;\n\t"
        "W_%=:\n\t"
        "mbarrier.try_wait.parity.acquire.cluster.shared::cta.b64 P, [%0], %1, 0x989680;\n\t"
        "@P bra.uni D_%=;\n\t"
        "bra.uni W_%=;\n\t"
        "D_%=:\n\t}"
        :: "r"(a), "r"(ph) : "memory");
}
__device__ __forceinline__ void remote_arrive(uint32_t a) {
    uint32_t zero = 0;
    asm volatile(
        "{\n\t.reg .b32 ra;\n\t"
        "mapa.shared::cluster.u32 ra, %0, %1;\n\t"
        "mbarrier.arrive.shared::cluster.b64 _, [ra];\n\t}"
        :: "r"(a), "r"(zero) : "memory");
}
__device__ __forceinline__ void mma_f16_cg2(uint32_t d, uint64_t da, uint64_t db,
                                            uint32_t idesc, bool en) {
    uint32_t e = en ? 1u : 0u, z = 0u;
    asm volatile(
        "{\n\t.reg .pred p;\n\t"
        "setp.ne.u32 p, %5, 0;\n\t"
        "tcgen05.mma.cta_group::2.kind::f16 [%0], %1, %2, %3, "
        "{%4, %4, %4, %4, %4, %4, %4, %4}, p;\n\t}"
        :: "r"(d), "l"(da), "l"(db), "r"(idesc), "r"(z), "r"(e) : "memory");
}
#define TC_LD32(r, a) \
    asm volatile("tcgen05.ld.sync.aligned.32x32b.x32.b32 " \
        "{%0, %1, %2, %3, %4, %5, %6, %7, %8, %9, %10, %11, %12, %13, %14, %15, " \
        "%16, %17, %18, %19, %20, %21, %22, %23, %24, %25, %26, %27, %28, %29, %30, %31}, [%32];" \
        : "=r"((r)[0]), "=r"((r)[1]), "=r"((r)[2]), "=r"((r)[3]), \
          "=r"((r)[4]), "=r"((r)[5]), "=r"((r)[6]), "=r"((r)[7]), \
          "=r"((r)[8]), "=r"((r)[9]), "=r"((r)[10]), "=r"((r)[11]), \
          "=r"((r)[12]), "=r"((r)[13]), "=r"((r)[14]), "=r"((r)[15]), \
          "=r"((r)[16]), "=r"((r)[17]), "=r"((r)[18]), "=r"((r)[19]), \
          "=r"((r)[20]), "=r"((r)[21]), "=r"((r)[22]), "=r"((r)[23]), \
          "=r"((r)[24]), "=r"((r)[25]), "=r"((r)[26]), "=r"((r)[27]), \
          "=r"((r)[28]), "=r"((r)[29]), "=r"((r)[30]), "=r"((r)[31]) \
        : "r"(a))
#define TC_WAIT_LD() asm volatile("tcgen05.wait::ld.sync.aligned;" ::: "memory")
#define TMA2D(dst, map, x, y, bar) \
    asm volatile("cp.async.bulk.tensor.2d.shared::cta.global.tile" \
                 ".mbarrier::complete_tx::bytes [%0], [%1, {%2, %3}], [%4];" \
                 :: "r"(dst), "l"(map), "r"(x), "r"(y), "r"(bar) : "memory")
#define MBAR_EXPECT(bar, bytes) \
    asm volatile("mbarrier.arrive.expect_tx.shared.b64 _, [%0], %1;" \
                 :: "r"(bar), "r"(bytes) : "memory")
#endif

__global__ void __launch_bounds__(256, 1) __cluster_dims__(2, 1, 1)
k_tcgemm(const __grid_constant__ CUtensorMap tmAh,
         const __grid_constant__ CUtensorMap tmAl,
         const __grid_constant__ CUtensorMap tmBh,
         const __grid_constant__ CUtensorMap tmBl,
         const float* __restrict__ vb, const float* __restrict__ kb,
         const float* __restrict__ n1, const float* __restrict__ n2,
         const float* __restrict__ hid)
{
#if !USE_TC
    (void)vb; (void)kb; (void)n1; (void)n2; (void)hid;
    return;
#else
    extern __shared__ char sm[];
    const int tid  = threadIdx.x;
    const int rank = blockIdx.x & 1;
    const int m0   = (blockIdx.x >> 1) * 256;
    const int nsup = blockIdx.y;                       // 0..19
    const bool isKey = (nsup >= 4);
    const uint32_t sb = sm2u(sm);
    // barriers: fullA[2]@16, fullB[2]@32, relA[2]@48, relB[2]@64, done[2]@80
    const uint32_t mb_fullA = sb + 16;
    const uint32_t mb_fullB = sb + 32;
    const uint32_t mb_relA  = sb + 48;
    const uint32_t mb_relB  = sb + 64;
    const uint32_t mb_done  = sb + 80;

    if (tid == 0) {
        #pragma unroll
        for (int s = 0; s < 2; s++) {
            asm volatile("mbarrier.init.shared.b64 [%0], 1;" :: "r"(mb_fullA + s * 8) : "memory");
            asm volatile("mbarrier.init.shared.b64 [%0], 1;" :: "r"(mb_fullB + s * 8) : "memory");
            asm volatile("mbarrier.init.shared.b64 [%0], 1;" :: "r"(mb_relA  + s * 8) : "memory");
            asm volatile("mbarrier.init.shared.b64 [%0], 1;" :: "r"(mb_relB  + s * 8) : "memory");
            asm volatile("mbarrier.init.shared.b64 [%0], 1;" :: "r"(mb_done  + s * 8) : "memory");
        }
    }
    if (tid < 32) {
        asm volatile("tcgen05.alloc.cta_group::2.sync.aligned.shared::cta.b32 [%0], 512;"
                     :: "r"(sb) : "memory");
    }
    __syncthreads();
    uint32_t tmem;
    asm volatile("ld.shared.b32 %0, [%1];" : "=r"(tmem) : "r"(sb));
    asm volatile("barrier.cluster.arrive.aligned;" ::: "memory");
    asm volatile("barrier.cluster.wait.aligned;"   ::: "memory");

    const uint32_t idesc = (1u << 4) | (1u << 7) | (1u << 10)
                         | ((256u / 8) << 17) | ((256u / 16) << 24);

    if (tid == 0) {
        const int ar  = m0 + rank * 128;                // A row base
        const int br0 = nsup * 512 + rank * 128;        // B rows half 0
        const int br1 = nsup * 512 + 256 + rank * 128;  // B rows half 1
        int fphA[2] = {0,0}, fphB[2] = {0,0};
        int rphA[2] = {0,0}, rphB[2] = {0,0};
        int dph [2] = {0,0};

        auto issue = [&](int kc, int s) {
            const uint32_t d0 = sb + 1024 + s * STAGE_B;
            const int x = kc * 128;
            // A-half: Ah + Bh (48KB) -> fullA
            MBAR_EXPECT(mb_fullA + s * 8, 49152u);
            TMA2D(d0,          &tmAh, x, ar,  mb_fullA + s * 8);
            TMA2D(d0 + 32768,  &tmBh, x, br0, mb_fullA + s * 8);
            TMA2D(d0 + 49152,  &tmBh, x, br1, mb_fullA + s * 8);
            // B-half (value tiles only): Al + Bl -> fullB
            if (!isKey) {
                MBAR_EXPECT(mb_fullB + s * 8, 49152u);
                TMA2D(d0 + 16384,  &tmAl, x, ar,  mb_fullB + s * 8);
                TMA2D(d0 + 65536,  &tmBl, x, br0, mb_fullB + s * 8);
                TMA2D(d0 + 81920,  &tmBl, x, br1, mb_fullB + s * 8);
            }
        };
        auto compute = [&](int kc, int sp) {
            if (rank == 0) {
                mbar_wait(mb_fullA + sp * 8, fphA[sp]); fphA[sp] ^= 1;
                mbar_wait(mb_relA  + sp * 8, rphA[sp]); rphA[sp] ^= 1;
                const uint32_t a = sb + 1024 + sp * STAGE_B;
                const uint64_t dAh = mk_desc(a);
                #pragma unroll
                for (int h = 0; h < 2; h++) {
                    const uint64_t dBh = mk_desc(a + 32768 + h * 16384);
                    const uint32_t dst = tmem + h * 256;
                    #pragma unroll
                    for (int ks = 0; ks < 4; ks++)
                        mma_f16_cg2(dst, dAh + ks * 2, dBh + ks * 2, idesc,
                                    !(kc == 0 && ks == 0));
                }
                if (!isKey) {
                    mbar_wait(mb_fullB + sp * 8, fphB[sp]); fphB[sp] ^= 1;
                    mbar_wait(mb_relB  + sp * 8, rphB[sp]); rphB[sp] ^= 1;
                    const uint64_t dAl = mk_desc(a + 16384);
                    #pragma unroll
                    for (int h = 0; h < 2; h++) {
                        const uint64_t dBh = mk_desc(a + 32768 + h * 16384);
                        const uint64_t dBl = mk_desc(a + 65536 + h * 16384);
                        const uint32_t dst = tmem + h * 256;
                        #pragma unroll
                        for (int ks = 0; ks < 4; ks++) {
                            mma_f16_cg2(dst, dAh + ks * 2, dBl + ks * 2, idesc, true);
                            mma_f16_cg2(dst, dAl + ks * 2, dBh + ks * 2, idesc, true);
                        }
                    }
                }
                asm volatile(
                    "tcgen05.commit.cta_group::2.mbarrier::arrive::one.shared::cluster"
                    ".multicast::cluster.b64 [%0], %1;"
                    :: "r"(mb_done + sp * 8), "h"((uint16_t)3) : "memory");
            } else {
                mbar_wait(mb_fullA + sp * 8, fphA[sp]); fphA[sp] ^= 1;
                remote_arrive(mb_relA + sp * 8);
                if (!isKey) {
                    mbar_wait(mb_fullB + sp * 8, fphB[sp]); fphB[sp] ^= 1;
                    remote_arrive(mb_relB + sp * 8);
                }
            }
        };

        #pragma unroll 1
        for (int kc = 0; kc < 16; kc++) {
            const int s = kc & 1;
            if (kc >= 2) { mbar_wait(mb_done + s * 8, dph[s]); dph[s] ^= 1; }
            issue(kc, s);
            if (kc >= 1) compute(kc - 1, s ^ 1);
        }
        compute(15, 1);
        mbar_wait(mb_done + 8, dph[1]);   // all 16 chunks' MMAs retired
    }
    __syncthreads();
    asm volatile("tcgen05.fence::after_thread_sync;" ::: "memory");

    // -------- coalesced epilogue (per-warp 32x33 SMEM transpose tile) --------
    const int w = tid >> 5, lane = tid & 31;
    const int h  = w >> 2;                      // col half (0: 0-255, 1: 256-511)
    const int rg = w & 3;                       // row group within CTA
    const int r0 = m0 + rank * 128 + rg * 32;
    const int r  = r0 + lane;
    float* tile = (float*)(sm + 1024) + w * (32 * 33);

    if (nsup < 4) {
        // ---- value projection: vp = D + vb, accumulate sum(vp^2) ----
        float vsq = 0.f;
        const int nb0 = nsup * 512 + h * 256;
        #pragma unroll
        for (int q = 0; q < 8; q++) {
            uint32_t d[32];
            TC_LD32(d, tmem + h * 256 + q * 32);
            TC_WAIT_LD();
            const int nb = nb0 + q * 32;
            #pragma unroll
            for (int c = 0; c < 32; c++) {
                float o = __uint_as_float(d[c]) + __ldg(vb + nb + c);
                vsq = fmaf(o, o, vsq);
                tile[lane * 33 + c] = o;
            }
            __syncwarp();
            #pragma unroll
            for (int rr = 0; rr < 32; rr++)
                g_vp[(size_t)(r0 + rr) * HIDn + nb + lane] = tile[rr * 33 + lane];
            __syncwarp();
        }
        g_vsq[r * 16 + nsup * 2 + h] = vsq;
    } else {
        // ---- keys (hc-interleaved): reduce to gate partials + hid^2 partials ----
        const int q = nsup - 4;                  // 0..15 d-chunk
        float pn[2] = {0.f, 0.f}, ps[2] = {0.f, 0.f};
        float hsq = 0.f;
        #pragma unroll
        for (int dq = 0; dq < 4; dq++) {
            const int dwin = q * 128 + dq * 32;
            #pragma unroll
            for (int rr = 0; rr < 32; rr++)      // coalesced hid stage
                tile[rr * 33 + lane] = __ldg(hid + (size_t)(r0 + rr) * HIDn + dwin + lane);
            __syncwarp();
            if (h == 0) {                        // hid row-rms partial (once per q)
                #pragma unroll
                for (int c = 0; c < 32; c++) {
                    float t = tile[lane * 33 + c];
                    hsq = fmaf(t, t, hsq);
                }
            }
            #pragma unroll
            for (int hcl = 0; hcl < 2; hcl++) {
                const int hc = h * 2 + hcl;
                uint32_t d[32];
                TC_LD32(d, tmem + h * 256 + hcl * 128 + dq * 32);
                TC_WAIT_LD();
                const int nb = hc * HIDn + dwin;
                #pragma unroll
                for (int c = 0; c < 32; c++) {
                    float kv = __uint_as_float(d[c]) + __ldg(kb + nb + c);
                    float w12 = __ldg(n1 + nb + c) * __ldg(n2 + nb + c);
                    pn[hcl] = fmaf(kv * w12, tile[lane * 33 + c], pn[hcl]);
                    ps[hcl] = fmaf(kv, kv, ps[hcl]);
                }
            }
            __syncwarp();
        }
        if (h == 0) g_hsq[r * 16 + q] = hsq;
        #pragma unroll
        for (int hcl = 0; hcl < 2; hcl++) {
            const int hc = h * 2 + hcl;
            g_pnum[((size_t)r * HCn + hc) * 16 + q] = pn[hcl];
            g_psq [((size_t)r * HCn + hc) * 16 + q] = ps[hcl];
        }
    }

    __syncthreads();
    if (tid < 32) {
        asm volatile("tcgen05.relinquish_alloc_permit.cta_group::2.sync.aligned;");
        asm volatile("tcgen05.dealloc.cta_group::2.sync.aligned.b32 %0, 512;" :: "r"(tmem));
    }
    asm volatile("barrier.cluster.arrive.aligned;" ::: "memory");
    asm volatile("barrier.cluster.wait.aligned;"   ::: "memory");
#endif
}

// ============ fallback: mma.sync bf16x3 pipelined GEMM (plain sm_103) ========
// (dead on sm_103a; launch is skipped host-side when device cc == 10.3)
#define FB_STAGE 40960
#define FB_SMEM  (3 * FB_STAGE)

#define LDSM4(r, addr) \
    asm volatile("ldmatrix.sync.aligned.m8n8.x4.shared.b16 {%0,%1,%2,%3}, [%4];" \
        : "=r"((r)[0]), "=r"((r)[1]), "=r"((r)[2]), "=r"((r)[3]) : "r"(addr))

#define MMA16816(c, a, b) \
    asm volatile("mma.sync.aligned.m16n8k16.row.col.f32.bf16.bf16.f32 " \
        "{%0,%1,%2,%3}, {%4,%5,%6,%7}, {%8,%9}, {%0,%1,%2,%3};" \
        : "+f"((c)[0]), "+f"((c)[1]), "+f"((c)[2]), "+f"((c)[3]) \
        : "r"((a)[0]), "r"((a)[1]), "r"((a)[2]), "r"((a)[3]), \
          "r"((b)[0]), "r"((b)[1]))

__global__ void __launch_bounds__(256, 1)
k_gemm_fb(const float* __restrict__ vb, const float* __restrict__ kb,
          const float* __restrict__ n1, const float* __restrict__ n2,
          const float* __restrict__ hid)
{
#if USE_TC
    (void)vb; (void)kb; (void)n1; (void)n2; (void)hid;
    return;
#else
    extern __shared__ char smem[];
    const uint32_t sb = sm2u(smem);
    const int tid = threadIdx.x;
    const int ntile = blockIdx.x;
    const int m0 = blockIdx.y * 128;
    const int n0 = ntile * 128;

    const char* gA_h = (const char*)(g_embh + (size_t)m0 * ENGn);
    const char* gA_l = (const char*)(g_embl + (size_t)m0 * ENGn);
    const char* gB_h = (const char*)(g_wth + (size_t)n0 * ENGn);
    const char* gB_l = (const char*)(g_wtl + (size_t)n0 * ENGn);

    const int ch = tid & 3;
    auto load_stage = [&](int s, int kc) {
        #pragma unroll
        for (int i = 0; i < 8; i++) {
            const int tsel = i >> 1;
            const int row = (((i & 1) << 8) + tid) >> 2;
            const char* src = (tsel == 0 ? gA_h : tsel == 1 ? gA_l :
                               tsel == 2 ? gB_h : gB_l)
                              + (size_t)row * 2048 + kc * 64 + ch * 16;
            uint32_t d = sb + s * FB_STAGE + tsel * 10240 + row * 80 + ch * 16;
            asm volatile("cp.async.cg.shared.global [%0], [%1], 16;"
                         :: "r"(d), "l"(src));
        }
        asm volatile("cp.async.commit_group;" ::: "memory");
    };

    load_stage(0, 0);
    load_stage(1, 1);

    float acc[4][4][4];
    #pragma unroll
    for (int i = 0; i < 4; i++)
        #pragma unroll
        for (int j = 0; j < 4; j++)
            #pragma unroll
            for (int q = 0; q < 4; q++) acc[i][j][q] = 0.f;

    const int lane = tid & 31, w = tid >> 5;
    const int wm = w >> 2, wn = w & 3;
    const uint32_t aRow   = wm * 64 + (lane & 15);
    const uint32_t aChunk = (lane >> 4) * 16;
    const int g = lane >> 3;
    const uint32_t bRow   = wn * 32 + ((g >> 1) & 1) * 8 + (lane & 7);
    const uint32_t bChunk = (g & 1) * 16;

    for (int kt = 0; kt < 32; kt++) {
        if (kt + 2 < 32) load_stage((kt + 2) % 3, kt + 2);
        else asm volatile("cp.async.commit_group;" ::: "memory");
        asm volatile("cp.async.wait_group 2;" ::: "memory");
        __syncthreads();

        const uint32_t st = sb + (kt % 3) * FB_STAGE;
        #pragma unroll
        for (int hh = 0; hh < 2; hh++) {
            uint32_t ah[4][4], al[4][4], bh[4][2], bl[4][2];
            #pragma unroll
            for (int mi = 0; mi < 4; mi++) {
                uint32_t ra = st + (aRow + mi * 16) * 80 + hh * 32 + aChunk;
                LDSM4(ah[mi], ra);
                LDSM4(al[mi], ra + 10240);
            }
            #pragma unroll
            for (int p = 0; p < 2; p++) {
                uint32_t rb = st + 20480 + (bRow + p * 16) * 80 + hh * 32 + bChunk;
                uint32_t r[4];
                LDSM4(r, rb);
                bh[2*p][0] = r[0]; bh[2*p][1] = r[1];
                bh[2*p+1][0] = r[2]; bh[2*p+1][1] = r[3];
                LDSM4(r, rb + 10240);
                bl[2*p][0] = r[0]; bl[2*p][1] = r[1];
                bl[2*p+1][0] = r[2]; bl[2*p+1][1] = r[3];
            }
            #pragma unroll
            for (int mi = 0; mi < 4; mi++)
                #pragma unroll
                for (int ni = 0; ni < 4; ni++) {
                    MMA16816(acc[mi][ni], ah[mi], bh[ni]);
                    MMA16816(acc[mi][ni], ah[mi], bl[ni]);
                    MMA16816(acc[mi][ni], al[mi], bh[ni]);
                }
        }
        __syncthreads();
    }

    float* sRed = (float*)smem;
    const int tq = lane & 3, rq = lane >> 2;

    if (ntile < 16) {
        #pragma unroll
        for (int mi = 0; mi < 4; mi++) {
            float vs0 = 0.f, vs1 = 0.f;
            const int r0 = m0 + wm * 64 + mi * 16 + rq;
            #pragma unroll
            for (int ni = 0; ni < 4; ni++) {
                const int n = n0 + wn * 32 + ni * 8 + tq * 2;
                float b0 = vb[n], b1 = vb[n + 1];
                float v00 = acc[mi][ni][0] + b0, v01 = acc[mi][ni][1] + b1;
                float v10 = acc[mi][ni][2] + b0, v11 = acc[mi][ni][3] + b1;
                *(float2*)(g_vp + (size_t)r0 * HIDn + n)       = make_float2(v00, v01);
                *(float2*)(g_vp + (size_t)(r0 + 8) * HIDn + n) = make_float2(v10, v11);
                vs0 += v00 * v00 + v01 * v01;
                vs1 += v10 * v10 + v11 * v11;
            }
            vs0 += __shfl_xor_sync(~0u, vs0, 1); vs0 += __shfl_xor_sync(~0u, vs0, 2);
            vs1 += __shfl_xor_sync(~0u, vs1, 1); vs1 += __shfl_xor_sync(~0u, vs1, 2);
            if (tq == 0) {
                int lr = wm * 64 + mi * 16 + rq;
                sRed[wn * 128 + lr]     = vs0;
                sRed[wn * 128 + lr + 8] = vs1;
            }
        }
        __syncthreads();
        if (tid < 128) {
            float s = sRed[tid] + sRed[128 + tid] + sRed[256 + tid] + sRed[384 + tid];
            g_vsq[(m0 + tid) * 16 + ntile] = s;
        }
    } else {
        const int kbase = (ntile - 16) * 128;
        const int hc = (kbase >> 7) & 3;
        const int q  = kbase >> 9;
        float* sPn = sRed;
        float* sPs = sRed + 512;
        #pragma unroll
        for (int mi = 0; mi < 4; mi++) {
            float pn0 = 0.f, ps0 = 0.f, pn1 = 0.f, ps1 = 0.f;
            const int r0 = m0 + wm * 64 + mi * 16 + rq;
            #pragma unroll
            for (int ni = 0; ni < 4; ni++) {
                const int cl = wn * 32 + ni * 8 + tq * 2;
                const int dd = q * 128 + cl;
                const int nb = hc * HIDn + dd;
                float b0 = kb[nb], b1 = kb[nb + 1];
                float w0 = n1[nb] * n2[nb], w1 = n1[nb + 1] * n2[nb + 1];
                float k00 = acc[mi][ni][0] + b0, k01 = acc[mi][ni][1] + b1;
                float k10 = acc[mi][ni][2] + b0, k11 = acc[mi][ni][3] + b1;
                const float* h0 = hid + (size_t)r0 * HIDn + dd;
                const float* h1 = hid + (size_t)(r0 + 8) * HIDn + dd;
                pn0 += k00 * w0 * h0[0] + k01 * w1 * h0[1];
                ps0 += k00 * k00 + k01 * k01;
                pn1 += k10 * w0 * h1[0] + k11 * w1 * h1[1];
                ps1 += k10 * k10 + k11 * k11;
            }
            pn0 += __shfl_xor_sync(~0u, pn0, 1); pn0 += __shfl_xor_sync(~0u, pn0, 2);
            ps0 += __shfl_xor_sync(~0u, ps0, 1); ps0 += __shfl_xor_sync(~0u, ps0, 2);
            pn1 += __shfl_xor_sync(~0u, pn1, 1); pn1 += __shfl_xor_sync(~0u, pn1, 2);
            ps1 += __shfl_xor_sync(~0u, ps1, 1); ps1 += __shfl_xor_sync(~0u, ps1, 2);
            if (tq == 0) {
                int lr = wm * 64 + mi * 16 + rq;
                sPn[wn * 128 + lr]     = pn0;  sPn[wn * 128 + lr + 8] = pn1;
                sPs[wn * 128 + lr]     = ps0;  sPs[wn * 128 + lr + 8] = ps1;
            }
        }
        __syncthreads();
        if (tid < 128) {
            float pn = sPn[tid] + sPn[128 + tid] + sPn[256 + tid] + sPn[384 + tid];
            float ps = sPs[tid] + sPs[128 + tid] + sPs[256 + tid] + sPs[384 + tid];
            g_pnum[((size_t)(m0 + tid) * HCn + hc) * 16 + q] = pn;
            g_psq [((size_t)(m0 + tid) * HCn + hc) * 16 + q] = ps;
        }
    }
#endif
}

// ---------------- K4: gates, alpha, sgate (one warp per row) ----------------
__global__ void k_gate()
{
    const int row  = blockIdx.x;
    const int lane = threadIdx.x;

    float v = (lane < 16) ? g_vsq[row * 16 + lane] : 0.f;
#if USE_TC
    float hv = (lane < 16) ? g_hsq[row * 16 + lane] : 0.f;
#endif
    #pragma unroll
    for (int q = 16; q > 0; q >>= 1) {
        v += __shfl_down_sync(0xffffffffu, v, q);
#if USE_TC
        hv += __shfl_down_sync(0xffffffffu, hv, q);
#endif
    }
    const float smsq = __shfl_sync(0xffffffffu, v, 0) * (1.f / HIDn);
#if USE_TC
    const float invq = rsqrtf(__shfl_sync(0xffffffffu, hv, 0) * (1.f / HIDn) + EPS_RMS);
#else
    const float invq = g_invq[row];
#endif

    const int g = lane >> 3, j = lane & 7;
    const float* pn = g_pnum + ((size_t)row * HCn + g) * 16;
    const float* pq = g_psq  + ((size_t)row * HCn + g) * 16;
    float num = pn[j] + pn[j + 8];
    float sq  = pq[j] + pq[j + 8];
    #pragma unroll
    for (int q = 4; q > 0; q >>= 1) {
        num += __shfl_down_sync(0xffffffffu, num, q, 8);
        sq  += __shfl_down_sync(0xffffffffu, sq,  q, 8);
    }
    float gate = 0.f;
    if (j == 0) {
        float irk = rsqrtf(sq * (1.f / HIDn) + EPS_RMS);
        float gg  = num * irk * invq * 0.022097086912079608f;   // 1/sqrt(2048)
        float sgn = (gg > 0.f) ? 1.f : ((gg < 0.f) ? -1.f : 0.f);
        float gs  = sgn * sqrtf(fmaxf(fabsf(gg), 1e-6f));
        gate = 1.f / (1.f + __expf(-gs));
        g_alpha[(size_t)row * HCn + g] = gate * rsqrtf(gate * gate * smsq + EPS_SC);
    }
    float sg = __shfl_sync(0xffffffffu, gate, 0) + __shfl_sync(0xffffffffu, gate, 8)
             + __shfl_sync(0xffffffffu, gate, 16) + __shfl_sync(0xffffffffu, gate, 24);
    if (lane == 0) g_sgate[row] = sg;
}

// ---------------- K5: fused dilated depthwise conv + silu + hc-sum ----------
// (vp is L2-resident, so the 4-tap re-reads are L2 hits)
__global__ void k_out(const float* __restrict__ scw,
                      const float* __restrict__ cw,
                      float* __restrict__ out)
{
    const int idx = blockIdx.x * 256 + threadIdx.x;
    if (idx >= Mn * HIDn / 4) return;
    const int row = idx >> 9;
    const int c   = (idx & 511) << 2;
    const int b = row / Ln;
    const int t = row - b * Ln;

    float v[4][4];
    float al[4][4];
    #pragma unroll
    for (int k = 0; k < 4; k++) {
        int tt = t + 3 * k - 9;
        if (tt >= 0) {
            int r2 = b * Ln + tt;
            float4 vv = *(const float4*)(g_vp + (size_t)r2 * HIDn + c);
            v[k][0] = vv.x; v[k][1] = vv.y; v[k][2] = vv.z; v[k][3] = vv.w;
            #pragma unroll
            for (int g = 0; g < 4; g++) al[k][g] = g_alpha[(size_t)r2 * HCn + g];
        } else {
            #pragma unroll
            for (int j = 0; j < 4; j++) { v[k][j] = 0.f; al[k][j] = 0.f; }
        }
    }

    const float sgate = g_sgate[row];
    float o[4];
    #pragma unroll
    for (int j = 0; j < 4; j++) o[j] = sgate * v[3][j];

    #pragma unroll
    for (int g = 0; g < 4; g++) {
        float4 sw = *(const float4*)(scw + g * HIDn + c);
        float swv[4] = {sw.x, sw.y, sw.z, sw.w};
        #pragma unroll
        for (int j = 0; j < 4; j++) {
            const float4 w = *(const float4*)(cw + ((size_t)(g * HIDn + c + j)) * 4);
            float y = w.x * al[0][g] * v[0][j]
                    + w.y * al[1][g] * v[1][j]
                    + w.z * al[2][g] * v[2][j]
                    + w.w * al[3][g] * v[3][j];
            y *= swv[j];
            o[j] += y / (1.f + __expf(-y));
        }
    }
    *(float4*)(out + (size_t)row * HIDn + c) = make_float4(o[0], o[1], o[2], o[3]);
}

// ---------------- host: tensormap construction + launch ----------------
typedef CUresult (*PFN_tmEncode)(
    CUtensorMap*, CUtensorMapDataType, cuuint32_t, void*,
    const cuuint64_t*, const cuuint64_t*, const cuuint32_t*, const cuuint32_t*,
    CUtensorMapInterleave, CUtensorMapSwizzle, CUtensorMapL2promotion,
    CUtensorMapFloatOOBfill);

static void encode_map(PFN_tmEncode fn, CUtensorMap* tm, void* base, unsigned rows)
{
    cuuint64_t dims[2]    = {2048ull, (cuuint64_t)rows};  // bytes per row, rows
    cuuint64_t strides[1] = {2048ull};
    cuuint32_t box[2]     = {128u, 128u};
    cuuint32_t es[2]      = {1u, 1u};
    fn(tm, CU_TENSOR_MAP_DATA_TYPE_UINT8, 2, base, dims, strides, box, es,
       CU_TENSOR_MAP_INTERLEAVE_NONE, CU_TENSOR_MAP_SWIZZLE_128B,
       CU_TENSOR_MAP_L2_PROMOTION_L2_128B, CU_TENSOR_MAP_FLOAT_OOB_FILL_NONE);
}

extern "C" void kernel_launch(void* const* d_in, const int* in_sizes, int n_in,
                              void* d_out, int out_size)
{
    (void)in_sizes; (void)n_in; (void)out_size;
    const float* hid = (const float*)d_in[0];
    const void*  ids = d_in[1];
    const float* tab = (const float*)d_in[2];
    const float* vw  = (const float*)d_in[3];
    const float* vb  = (const float*)d_in[4];
    const float* kw  = (const float*)d_in[5];
    const float* kb  = (const float*)d_in[6];
    const float* n1  = (const float*)d_in[7];
    const float* n2  = (const float*)d_in[8];
    const float* scw = (const float*)d_in[9];
    const float* cw  = (const float*)d_in[10];
    float* out = (float*)d_out;

    PFN_tmEncode fn = nullptr;
    cudaDriverEntryPointQueryResult qres;
    cudaGetDriverEntryPointByVersion("cuTensorMapEncodeTiled", (void**)&fn,
                                     12000, cudaEnableDefault, &qres);
    void *pAh, *pAl, *pBh, *pBl;
    cudaGetSymbolAddress(&pAh, g_embh);
    cudaGetSymbolAddress(&pAl, g_embl);
    cudaGetSymbolAddress(&pBh, g_wth);
    cudaGetSymbolAddress(&pBl, g_wtl);
    CUtensorMap tmAh{}, tmAl{}, tmBh{}, tmBl{};
    if (fn) {
        encode_map(fn, &tmAh, pAh, Mn);
        encode_map(fn, &tmAl, pAl, Mn);
        encode_map(fn, &tmBh, pBh, NTOT);
        encode_map(fn, &tmBl, pBl, NTOT);
    }

    int ccM = 0, ccm = 0, dev = 0;
    cudaGetDevice(&dev);
    cudaDeviceGetAttribute(&ccM, cudaDevAttrComputeCapabilityMajor, dev);
    cudaDeviceGetAttribute(&ccm, cudaDevAttrComputeCapabilityMinor, dev);
    const bool isSm103 = (ccM == 10 && ccm == 3);

    cudaFuncSetAttribute(k_tcgemm,  cudaFuncAttributeMaxDynamicSharedMemorySize, GSMEM);
    cudaFuncSetAttribute(k_gemm_fb, cudaFuncAttributeMaxDynamicSharedMemorySize, FB_SMEM);

    k_prep<<<Mn + (NTOT / 64) * (ENGn / 64), 256>>>(ids, tab, hid, vw, kw);
    if (!isSm103)
        k_gemm_fb<<<dim3(80, 64), 256, FB_SMEM>>>(vb, kb, n1, n2, hid);
    k_tcgemm<<<dim3(64, 20), 256, GSMEM>>>(tmAh, tmAl, tmBh, tmBl,
                                           vb, kb, n1, n2, hid);
    k_gate<<<Mn, 32>>>();
    k_out<<<(Mn * HIDn / 4 + 255) / 256, 256>>>(scw, cw, out);
}

// round 15
// speedup vs baseline: 1.2870x; 1.0616x over previous
#include <cuda_runtime.h>
#include <cuda.h>
#include <cuda_bf16.h>
#include <cstdint>

#define Bn 2
#define Ln 4096
#define Mn (Bn*Ln)          // 8192 rows
#define HIDn 2048
#define ENGn 1024
#define NHEADn 16
#define VOCABn 129280
#define HCn 4
#define NTOT 10240          // 2048 value cols + 4*2048 key cols
#define SCHUNK 32           // k_out: outputs per thread (t stride 3)
#define EPS_RMS 1.1920929e-07f
#define EPS_SC  1e-5f

#if defined(__CUDA_ARCH__) && (__CUDA_ARCH__ == 1030) && defined(__CUDA_ARCH_FEAT_SM103_ALL)
#define USE_TC 1
#else
#define USE_TC 0
#endif

// ---------------- scratch (device globals: allocation-free) ----------------
__device__ __nv_bfloat16 g_embh[(size_t)Mn * ENGn];
__device__ __nv_bfloat16 g_embl[(size_t)Mn * ENGn];
__device__ __nv_bfloat16 g_wth [(size_t)NTOT * ENGn];  // W^T hi (keys hc-interleaved)
__device__ __nv_bfloat16 g_wtl [(size_t)NTOT * ENGn];  // W^T lo (key rows stay zero)
__device__ float g_vp [(size_t)Mn * HIDn];
__device__ float g_invq[Mn];                           // used by non-TC path only
__device__ float g_hsq [Mn * 16];                      // TC path: hid^2 partials
__device__ float g_vsq [Mn * 16];
__device__ float g_pnum[Mn * HCn * 16];
__device__ float g_psq [Mn * HCn * 16];
__device__ float g_alpha[Mn * HCn];
__device__ float g_sgate[Mn];

__device__ __forceinline__ uint32_t sm2u(const void* p) {
    return (uint32_t)__cvta_generic_to_shared(p);
}

// ---------------- K1: fused gather (+rms on non-TC) and weight transpose ----
__global__ void k_prep(const void* __restrict__ ids_raw,
                       const float* __restrict__ tab,
                       const float* __restrict__ hid,
                       const float* __restrict__ vw,
                       const float* __restrict__ kw)
{
    __shared__ float ts[64][65];
    const int tid = threadIdx.x;

    if (blockIdx.x < Mn) {
        // ---------------- gather ----------------
        const int row = blockIdx.x;
        int* sid = (int*)&ts[0][0];

        if (tid == 0) {
            const long long* p64 = (const long long*)ids_raw;
            bool is64 = true;
            #pragma unroll
            for (int i = 0; i < 8; i++) {
                long long v = p64[i];
                if (v < 0 || v >= (long long)VOCABn) { is64 = false; break; }
            }
            if (is64) {
                const long long* p = p64 + (size_t)row * NHEADn;
                for (int h = 0; h < NHEADn; h++) sid[h] = (int)p[h];
            } else {
                const int* p = ((const int*)ids_raw) + (size_t)row * NHEADn;
                for (int h = 0; h < NHEADn; h++) sid[h] = p[h];
            }
        }
        __syncthreads();

        #pragma unroll
        for (int e = tid; e < ENGn; e += 256) {
            int h = e >> 6, d = e & 63;
            float v = tab[((size_t)h * VOCABn + (size_t)sid[h]) * 64 + d];
            __nv_bfloat16 hi = __float2bfloat16(v);
            __nv_bfloat16 lo = __float2bfloat16(v - __bfloat162float(hi));
            g_embh[(size_t)row * ENGn + e] = hi;
            g_embl[(size_t)row * ENGn + e] = lo;
        }

#if !USE_TC
        float* sbuf = (float*)&ts[1][0];
        float s = 0.f;
        const float* hr = hid + (size_t)row * HIDn;
        for (int i = tid; i < HIDn; i += 256) { float v = hr[i]; s += v * v; }
        int lane = tid & 31, wid = tid >> 5;
        #pragma unroll
        for (int q = 16; q > 0; q >>= 1) s += __shfl_down_sync(0xffffffffu, s, q);
        if (lane == 0) sbuf[wid] = s;
        __syncthreads();
        if (wid == 0) {
            s = (lane < 8) ? sbuf[lane] : 0.f;
            #pragma unroll
            for (int q = 4; q > 0; q >>= 1) s += __shfl_down_sync(0xffffffffu, s, q);
            if (lane == 0) g_invq[row] = rsqrtf(s * (1.f / HIDn) + EPS_RMS);
        }
#else
        (void)hid;
#endif
    } else {
        // ---------------- weight transpose ----------------
        const int wb = blockIdx.x - Mn;
        const int n0 = (wb % 160) * 64;
        const int k0 = (wb / 160) * 64;
        const int s  = n0 >> 11;
        const float* W = (s == 0) ? vw : kw + (size_t)(s - 1) * ENGn * HIDn;
        const int col0 = n0 & 2047;
        const int tx  = tid & 63;
        const int ty4 = tid >> 6;

        #pragma unroll
        for (int i = 0; i < 16; i++) {
            int kk = ty4 + i * 4;
            ts[kk][tx] = W[(size_t)(k0 + kk) * HIDn + col0 + tx];
        }
        __syncthreads();
        #pragma unroll
        for (int i = 0; i < 16; i++) {
            int nn = ty4 + i * 4;
            float v = ts[tx][nn];
            __nv_bfloat16 hi = __float2bfloat16(v);
            if (s == 0) {
                int orow = n0 + nn;
                size_t o = (size_t)orow * ENGn + k0 + tx;
                g_wth[o] = hi;
                g_wtl[o] = __float2bfloat16(v - __bfloat162float(hi));
            } else {
                int d = col0 + nn;
                int orow = 2048 + ((d >> 7) << 9) + ((s - 1) << 7) + (d & 127);
                g_wth[(size_t)orow * ENGn + k0 + tx] = hi;   // lo stays zero
            }
        }
    }
}

// ================= tcgen05 path (sm_103a feature target) =====================
// cluster pair computes D[256 M, 512 N] over K=1024; 16 kchunks of 64.
// value tiles (nsup<4): 3-term bf16x3. key tiles: pure bf16 (AhBh only).
#define STAGE_B 98304
#define GSMEM   (1024 + 2 * STAGE_B)

#if USE_TC
__device__ __forceinline__ uint64_t mk_desc(uint32_t addr) {
    return 0x4000404000010000ull | (uint64_t)((addr >> 4) & 0x3FFF);
}
__device__ __forceinline__ void mbar_wait(uint32_t a, int ph) {
    asm volatile(
        "{\n\t.reg .pred P;\n\t"
        "W_%=:\n\t"
        "mbarrier.try_wait.parity.acquire.cluster.shared::cta.b64 P, [%0], %1, 0x989680;\n\t"
        "@P bra.uni D_%=;\n\t"
        "bra.uni W_%=;\n\t"
        "D_%=:\n\t}"
        :: "r"(a), "r"(ph) : "memory");
}
__device__ __forceinline__ void remote_arrive(uint32_t a) {
    uint32_t zero = 0;
    asm volatile(
        "{\n\t.reg .b32 ra;\n\t"
        "mapa.shared::cluster.u32 ra, %0, %1;\n\t"
        "mbarrier.arrive.shared::cluster.b64 _, [ra];\n\t}"
        :: "r"(a), "r"(zero) : "memory");
}
__device__ __forceinline__ void mma_f16_cg2(uint32_t d, uint64_t da, uint64_t db,
                                            uint32_t idesc, bool en) {
    uint32_t e = en ? 1u : 0u, z = 0u;
    asm volatile(
        "{\n\t.reg .pred p;\n\t"
        "setp.ne.u32 p, %5, 0;\n\t"
        "tcgen05.mma.cta_group::2.kind::f16 [%0], %1, %2, %3, "
        "{%4, %4, %4, %4, %4, %4, %4, %4}, p;\n\t}"
        :: "r"(d), "l"(da), "l"(db), "r"(idesc), "r"(z), "r"(e) : "memory");
}
#define TC_LD32(r, a) \
    asm volatile("tcgen05.ld.sync.aligned.32x32b.x32.b32 " \
        "{%0, %1, %2, %3, %4, %5, %6, %7, %8, %9, %10, %11, %12, %13, %14, %15, " \
        "%16, %17, %18, %19, %20, %21, %22, %23, %24, %25, %26, %27, %28, %29, %30, %31}, [%32];" \
        : "=r"((r)[0]), "=r"((r)[1]), "=r"((r)[2]), "=r"((r)[3]), \
          "=r"((r)[4]), "=r"((r)[5]), "=r"((r)[6]), "=r"((r)[7]), \
          "=r"((r)[8]), "=r"((r)[9]), "=r"((r)[10]), "=r"((r)[11]), \
          "=r"((r)[12]), "=r"((r)[13]), "=r"((r)[14]), "=r"((r)[15]), \
          "=r"((r)[16]), "=r"((r)[17]), "=r"((r)[18]), "=r"((r)[19]), \
          "=r"((r)[20]), "=r"((r)[21]), "=r"((r)[22]), "=r"((r)[23]), \
          "=r"((r)[24]), "=r"((r)[25]), "=r"((r)[26]), "=r"((r)[27]), \
          "=r"((r)[28]), "=r"((r)[29]), "=r"((r)[30]), "=r"((r)[31]) \
        : "r"(a))
#define TC_WAIT_LD() asm volatile("tcgen05.wait::ld.sync.aligned;" ::: "memory")
#define TMA2D(dst, map, x, y, bar) \
    asm volatile("cp.async.bulk.tensor.2d.shared::cta.global.tile" \
                 ".mbarrier::complete_tx::bytes [%0], [%1, {%2, %3}], [%4];" \
                 :: "r"(dst), "l"(map), "r"(x), "r"(y), "r"(bar) : "memory")
#define MBAR_EXPECT(bar, bytes) \
    asm volatile("mbarrier.arrive.expect_tx.shared.b64 _, [%0], %1;" \
                 :: "r"(bar), "r"(bytes) : "memory")
#endif

__global__ void __launch_bounds__(256, 1) __cluster_dims__(2, 1, 1)
k_tcgemm(const __grid_constant__ CUtensorMap tmAh,
         const __grid_constant__ CUtensorMap tmAl,
         const __grid_constant__ CUtensorMap tmBh,
         const __grid_constant__ CUtensorMap tmBl,
         const float* __restrict__ vb, const float* __restrict__ kb,
         const float* __restrict__ n1, const float* __restrict__ n2,
         const float* __restrict__ hid)
{
#if !USE_TC
    (void)vb; (void)kb; (void)n1; (void)n2; (void)hid;
    return;
#else
    extern __shared__ char sm[];
    const int tid  = threadIdx.x;
    const int rank = blockIdx.x & 1;
    const int m0   = (blockIdx.x >> 1) * 256;
    const int nsup = blockIdx.y;                       // 0..19
    const bool isKey = (nsup >= 4);
    const uint32_t sb = sm2u(sm);
    const uint32_t mb_fullA = sb + 16;
    const uint32_t mb_fullB = sb + 32;
    const uint32_t mb_relA  = sb + 48;
    const uint32_t mb_relB  = sb + 64;
    const uint32_t mb_done  = sb + 80;

    if (tid == 0) {
        #pragma unroll
        for (int s = 0; s < 2; s++) {
            asm volatile("mbarrier.init.shared.b64 [%0], 1;" :: "r"(mb_fullA + s * 8) : "memory");
            asm volatile("mbarrier.init.shared.b64 [%0], 1;" :: "r"(mb_fullB + s * 8) : "memory");
            asm volatile("mbarrier.init.shared.b64 [%0], 1;" :: "r"(mb_relA  + s * 8) : "memory");
            asm volatile("mbarrier.init.shared.b64 [%0], 1;" :: "r"(mb_relB  + s * 8) : "memory");
            asm volatile("mbarrier.init.shared.b64 [%0], 1;" :: "r"(mb_done  + s * 8) : "memory");
        }
    }
    if (tid < 32) {
        asm volatile("tcgen05.alloc.cta_group::2.sync.aligned.shared::cta.b32 [%0], 512;"
                     :: "r"(sb) : "memory");
    }
    __syncthreads();
    uint32_t tmem;
    asm volatile("ld.shared.b32 %0, [%1];" : "=r"(tmem) : "r"(sb));
    asm volatile("barrier.cluster.arrive.aligned;" ::: "memory");
    asm volatile("barrier.cluster.wait.aligned;"   ::: "memory");

    const uint32_t idesc = (1u << 4) | (1u << 7) | (1u << 10)
                         | ((256u / 8) << 17) | ((256u / 16) << 24);

    if (tid == 0) {
        const int ar  = m0 + rank * 128;
        const int br0 = nsup * 512 + rank * 128;
        const int br1 = nsup * 512 + 256 + rank * 128;
        int fphA[2] = {0,0}, fphB[2] = {0,0};
        int rphA[2] = {0,0}, rphB[2] = {0,0};
        int dph [2] = {0,0};

        auto issue = [&](int kc, int s) {
            const uint32_t d0 = sb + 1024 + s * STAGE_B;
            const int x = kc * 128;
            MBAR_EXPECT(mb_fullA + s * 8, 49152u);
            TMA2D(d0,          &tmAh, x, ar,  mb_fullA + s * 8);
            TMA2D(d0 + 32768,  &tmBh, x, br0, mb_fullA + s * 8);
            TMA2D(d0 + 49152,  &tmBh, x, br1, mb_fullA + s * 8);
            if (!isKey) {
                MBAR_EXPECT(mb_fullB + s * 8, 49152u);
                TMA2D(d0 + 16384,  &tmAl, x, ar,  mb_fullB + s * 8);
                TMA2D(d0 + 65536,  &tmBl, x, br0, mb_fullB + s * 8);
                TMA2D(d0 + 81920,  &tmBl, x, br1, mb_fullB + s * 8);
            }
        };
        auto compute = [&](int kc, int sp) {
            if (rank == 0) {
                mbar_wait(mb_fullA + sp * 8, fphA[sp]); fphA[sp] ^= 1;
                mbar_wait(mb_relA  + sp * 8, rphA[sp]); rphA[sp] ^= 1;
                const uint32_t a = sb + 1024 + sp * STAGE_B;
                const uint64_t dAh = mk_desc(a);
                #pragma unroll
                for (int h = 0; h < 2; h++) {
                    const uint64_t dBh = mk_desc(a + 32768 + h * 16384);
                    const uint32_t dst = tmem + h * 256;
                    #pragma unroll
                    for (int ks = 0; ks < 4; ks++)
                        mma_f16_cg2(dst, dAh + ks * 2, dBh + ks * 2, idesc,
                                    !(kc == 0 && ks == 0));
                }
                if (!isKey) {
                    mbar_wait(mb_fullB + sp * 8, fphB[sp]); fphB[sp] ^= 1;
                    mbar_wait(mb_relB  + sp * 8, rphB[sp]); rphB[sp] ^= 1;
                    const uint64_t dAl = mk_desc(a + 16384);
                    #pragma unroll
                    for (int h = 0; h < 2; h++) {
                        const uint64_t dBh = mk_desc(a + 32768 + h * 16384);
                        const uint64_t dBl = mk_desc(a + 65536 + h * 16384);
                        const uint32_t dst = tmem + h * 256;
                        #pragma unroll
                        for (int ks = 0; ks < 4; ks++) {
                            mma_f16_cg2(dst, dAh + ks * 2, dBl + ks * 2, idesc, true);
                            mma_f16_cg2(dst, dAl + ks * 2, dBh + ks * 2, idesc, true);
                        }
                    }
                }
                asm volatile(
                    "tcgen05.commit.cta_group::2.mbarrier::arrive::one.shared::cluster"
                    ".multicast::cluster.b64 [%0], %1;"
                    :: "r"(mb_done + sp * 8), "h"((uint16_t)3) : "memory");
            } else {
                mbar_wait(mb_fullA + sp * 8, fphA[sp]); fphA[sp] ^= 1;
                remote_arrive(mb_relA + sp * 8);
                if (!isKey) {
                    mbar_wait(mb_fullB + sp * 8, fphB[sp]); fphB[sp] ^= 1;
                    remote_arrive(mb_relB + sp * 8);
                }
            }
        };

        #pragma unroll 1
        for (int kc = 0; kc < 16; kc++) {
            const int s = kc & 1;
            if (kc >= 2) { mbar_wait(mb_done + s * 8, dph[s]); dph[s] ^= 1; }
            issue(kc, s);
            if (kc >= 1) compute(kc - 1, s ^ 1);
        }
        compute(15, 1);
        mbar_wait(mb_done + 8, dph[1]);
    }
    __syncthreads();
    asm volatile("tcgen05.fence::after_thread_sync;" ::: "memory");

    // -------- coalesced epilogue (per-warp 32x33 SMEM transpose tile) --------
    const int w = tid >> 5, lane = tid & 31;
    const int h  = w >> 2;
    const int rg = w & 3;
    const int r0 = m0 + rank * 128 + rg * 32;
    const int r  = r0 + lane;
    float* tile = (float*)(sm + 1024) + w * (32 * 33);

    if (nsup < 4) {
        float vsq = 0.f;
        const int nb0 = nsup * 512 + h * 256;
        #pragma unroll
        for (int q = 0; q < 8; q++) {
            uint32_t d[32];
            TC_LD32(d, tmem + h * 256 + q * 32);
            TC_WAIT_LD();
            const int nb = nb0 + q * 32;
            #pragma unroll
            for (int c = 0; c < 32; c++) {
                float o = __uint_as_float(d[c]) + __ldg(vb + nb + c);
                vsq = fmaf(o, o, vsq);
                tile[lane * 33 + c] = o;
            }
            __syncwarp();
            #pragma unroll
            for (int rr = 0; rr < 32; rr++)
                g_vp[(size_t)(r0 + rr) * HIDn + nb + lane] = tile[rr * 33 + lane];
            __syncwarp();
        }
        g_vsq[r * 16 + nsup * 2 + h] = vsq;
    } else {
        const int q = nsup - 4;
        float pn[2] = {0.f, 0.f}, ps[2] = {0.f, 0.f};
        float hsq = 0.f;
        #pragma unroll
        for (int dq = 0; dq < 4; dq++) {
            const int dwin = q * 128 + dq * 32;
            #pragma unroll
            for (int rr = 0; rr < 32; rr++)
                tile[rr * 33 + lane] = __ldg(hid + (size_t)(r0 + rr) * HIDn + dwin + lane);
            __syncwarp();
            if (h == 0) {
                #pragma unroll
                for (int c = 0; c < 32; c++) {
                    float t = tile[lane * 33 + c];
                    hsq = fmaf(t, t, hsq);
                }
            }
            #pragma unroll
            for (int hcl = 0; hcl < 2; hcl++) {
                const int hc = h * 2 + hcl;
                uint32_t d[32];
                TC_LD32(d, tmem + h * 256 + hcl * 128 + dq * 32);
                TC_WAIT_LD();
                const int nb = hc * HIDn + dwin;
                #pragma unroll
                for (int c = 0; c < 32; c++) {
                    float kv = __uint_as_float(d[c]) + __ldg(kb + nb + c);
                    float w12 = __ldg(n1 + nb + c) * __ldg(n2 + nb + c);
                    pn[hcl] = fmaf(kv * w12, tile[lane * 33 + c], pn[hcl]);
                    ps[hcl] = fmaf(kv, kv, ps[hcl]);
                }
            }
            __syncwarp();
        }
        if (h == 0) g_hsq[r * 16 + q] = hsq;
        #pragma unroll
        for (int hcl = 0; hcl < 2; hcl++) {
            const int hc = h * 2 + hcl;
            g_pnum[((size_t)r * HCn + hc) * 16 + q] = pn[hcl];
            g_psq [((size_t)r * HCn + hc) * 16 + q] = ps[hcl];
        }
    }

    __syncthreads();
    if (tid < 32) {
        asm volatile("tcgen05.relinquish_alloc_permit.cta_group::2.sync.aligned;");
        asm volatile("tcgen05.dealloc.cta_group::2.sync.aligned.b32 %0, 512;" :: "r"(tmem));
    }
    asm volatile("barrier.cluster.arrive.aligned;" ::: "memory");
    asm volatile("barrier.cluster.wait.aligned;"   ::: "memory");
#endif
}

// ============ fallback: mma.sync bf16x3 pipelined GEMM (plain sm_103) ========
#define FB_STAGE 40960
#define FB_SMEM  (3 * FB_STAGE)

#define LDSM4(r, addr) \
    asm volatile("ldmatrix.sync.aligned.m8n8.x4.shared.b16 {%0,%1,%2,%3}, [%4];" \
        : "=r"((r)[0]), "=r"((r)[1]), "=r"((r)[2]), "=r"((r)[3]) : "r"(addr))

#define MMA16816(c, a, b) \
    asm volatile("mma.sync.aligned.m16n8k16.row.col.f32.bf16.bf16.f32 " \
        "{%0,%1,%2,%3}, {%4,%5,%6,%7}, {%8,%9}, {%0,%1,%2,%3};" \
        : "+f"((c)[0]), "+f"((c)[1]), "+f"((c)[2]), "+f"((c)[3]) \
        : "r"((a)[0]), "r"((a)[1]), "r"((a)[2]), "r"((a)[3]), \
          "r"((b)[0]), "r"((b)[1]))

__global__ void __launch_bounds__(256, 1)
k_gemm_fb(const float* __restrict__ vb, const float* __restrict__ kb,
          const float* __restrict__ n1, const float* __restrict__ n2,
          const float* __restrict__ hid)
{
#if USE_TC
    (void)vb; (void)kb; (void)n1; (void)n2; (void)hid;
    return;
#else
    extern __shared__ char smem[];
    const uint32_t sb = sm2u(smem);
    const int tid = threadIdx.x;
    const int ntile = blockIdx.x;
    const int m0 = blockIdx.y * 128;
    const int n0 = ntile * 128;

    const char* gA_h = (const char*)(g_embh + (size_t)m0 * ENGn);
    const char* gA_l = (const char*)(g_embl + (size_t)m0 * ENGn);
    const char* gB_h = (const char*)(g_wth + (size_t)n0 * ENGn);
    const char* gB_l = (const char*)(g_wtl + (size_t)n0 * ENGn);

    const int ch = tid & 3;
    auto load_stage = [&](int s, int kc) {
        #pragma unroll
        for (int i = 0; i < 8; i++) {
            const int tsel = i >> 1;
            const int row = (((i & 1) << 8) + tid) >> 2;
            const char* src = (tsel == 0 ? gA_h : tsel == 1 ? gA_l :
                               tsel == 2 ? gB_h : gB_l)
                              + (size_t)row * 2048 + kc * 64 + ch * 16;
            uint32_t d = sb + s * FB_STAGE + tsel * 10240 + row * 80 + ch * 16;
            asm volatile("cp.async.cg.shared.global [%0], [%1], 16;"
                         :: "r"(d), "l"(src));
        }
        asm volatile("cp.async.commit_group;" ::: "memory");
    };

    load_stage(0, 0);
    load_stage(1, 1);

    float acc[4][4][4];
    #pragma unroll
    for (int i = 0; i < 4; i++)
        #pragma unroll
        for (int j = 0; j < 4; j++)
            #pragma unroll
            for (int q = 0; q < 4; q++) acc[i][j][q] = 0.f;

    const int lane = tid & 31, w = tid >> 5;
    const int wm = w >> 2, wn = w & 3;
    const uint32_t aRow   = wm * 64 + (lane & 15);
    const uint32_t aChunk = (lane >> 4) * 16;
    const int g = lane >> 3;
    const uint32_t bRow   = wn * 32 + ((g >> 1) & 1) * 8 + (lane & 7);
    const uint32_t bChunk = (g & 1) * 16;

    for (int kt = 0; kt < 32; kt++) {
        if (kt + 2 < 32) load_stage((kt + 2) % 3, kt + 2);
        else asm volatile("cp.async.commit_group;" ::: "memory");
        asm volatile("cp.async.wait_group 2;" ::: "memory");
        __syncthreads();

        const uint32_t st = sb + (kt % 3) * FB_STAGE;
        #pragma unroll
        for (int hh = 0; hh < 2; hh++) {
            uint32_t ah[4][4], al[4][4], bh[4][2], bl[4][2];
            #pragma unroll
            for (int mi = 0; mi < 4; mi++) {
                uint32_t ra = st + (aRow + mi * 16) * 80 + hh * 32 + aChunk;
                LDSM4(ah[mi], ra);
                LDSM4(al[mi], ra + 10240);
            }
            #pragma unroll
            for (int p = 0; p < 2; p++) {
                uint32_t rb = st + 20480 + (bRow + p * 16) * 80 + hh * 32 + bChunk;
                uint32_t r[4];
                LDSM4(r, rb);
                bh[2*p][0] = r[0]; bh[2*p][1] = r[1];
                bh[2*p+1][0] = r[2]; bh[2*p+1][1] = r[3];
                LDSM4(r, rb + 10240);
                bl[2*p][0] = r[0]; bl[2*p][1] = r[1];
                bl[2*p+1][0] = r[2]; bl[2*p+1][1] = r[3];
            }
            #pragma unroll
            for (int mi = 0; mi < 4; mi++)
                #pragma unroll
                for (int ni = 0; ni < 4; ni++) {
                    MMA16816(acc[mi][ni], ah[mi], bh[ni]);
                    MMA16816(acc[mi][ni], ah[mi], bl[ni]);
                    MMA16816(acc[mi][ni], al[mi], bh[ni]);
                }
        }
        __syncthreads();
    }

    float* sRed = (float*)smem;
    const int tq = lane & 3, rq = lane >> 2;

    if (ntile < 16) {
        #pragma unroll
        for (int mi = 0; mi < 4; mi++) {
            float vs0 = 0.f, vs1 = 0.f;
            const int r0 = m0 + wm * 64 + mi * 16 + rq;
            #pragma unroll
            for (int ni = 0; ni < 4; ni++) {
                const int n = n0 + wn * 32 + ni * 8 + tq * 2;
                float b0 = vb[n], b1 = vb[n + 1];
                float v00 = acc[mi][ni][0] + b0, v01 = acc[mi][ni][1] + b1;
                float v10 = acc[mi][ni][2] + b0, v11 = acc[mi][ni][3] + b1;
                *(float2*)(g_vp + (size_t)r0 * HIDn + n)       = make_float2(v00, v01);
                *(float2*)(g_vp + (size_t)(r0 + 8) * HIDn + n) = make_float2(v10, v11);
                vs0 += v00 * v00 + v01 * v01;
                vs1 += v10 * v10 + v11 * v11;
            }
            vs0 += __shfl_xor_sync(~0u, vs0, 1); vs0 += __shfl_xor_sync(~0u, vs0, 2);
            vs1 += __shfl_xor_sync(~0u, vs1, 1); vs1 += __shfl_xor_sync(~0u, vs1, 2);
            if (tq == 0) {
                int lr = wm * 64 + mi * 16 + rq;
                sRed[wn * 128 + lr]     = vs0;
                sRed[wn * 128 + lr + 8] = vs1;
            }
        }
        __syncthreads();
        if (tid < 128) {
            float s = sRed[tid] + sRed[128 + tid] + sRed[256 + tid] + sRed[384 + tid];
            g_vsq[(m0 + tid) * 16 + ntile] = s;
        }
    } else {
        const int kbase = (ntile - 16) * 128;
        const int hc = (kbase >> 7) & 3;
        const int q  = kbase >> 9;
        float* sPn = sRed;
        float* sPs = sRed + 512;
        #pragma unroll
        for (int mi = 0; mi < 4; mi++) {
            float pn0 = 0.f, ps0 = 0.f, pn1 = 0.f, ps1 = 0.f;
            const int r0 = m0 + wm * 64 + mi * 16 + rq;
            #pragma unroll
            for (int ni = 0; ni < 4; ni++) {
                const int cl = wn * 32 + ni * 8 + tq * 2;
                const int dd = q * 128 + cl;
                const int nb = hc * HIDn + dd;
                float b0 = kb[nb], b1 = kb[nb + 1];
                float w0 = n1[nb] * n2[nb], w1 = n1[nb + 1] * n2[nb + 1];
                float k00 = acc[mi][ni][0] + b0, k01 = acc[mi][ni][1] + b1;
                float k10 = acc[mi][ni][2] + b0, k11 = acc[mi][ni][3] + b1;
                const float* h0 = hid + (size_t)r0 * HIDn + dd;
                const float* h1 = hid + (size_t)(r0 + 8) * HIDn + dd;
                pn0 += k00 * w0 * h0[0] + k01 * w1 * h0[1];
                ps0 += k00 * k00 + k01 * k01;
                pn1 += k10 * w0 * h1[0] + k11 * w1 * h1[1];
                ps1 += k10 * k10 + k11 * k11;
            }
            pn0 += __shfl_xor_sync(~0u, pn0, 1); pn0 += __shfl_xor_sync(~0u, pn0, 2);
            ps0 += __shfl_xor_sync(~0u, ps0, 1); ps0 += __shfl_xor_sync(~0u, ps0, 2);
            pn1 += __shfl_xor_sync(~0u, pn1, 1); pn1 += __shfl_xor_sync(~0u, pn1, 2);
            ps1 += __shfl_xor_sync(~0u, ps1, 1); ps1 += __shfl_xor_sync(~0u, ps1, 2);
            if (tq == 0) {
                int lr = wm * 64 + mi * 16 + rq;
                sPn[wn * 128 + lr]     = pn0;  sPn[wn * 128 + lr + 8] = pn1;
                sPs[wn * 128 + lr]     = ps0;  sPs[wn * 128 + lr + 8] = ps1;
            }
        }
        __syncthreads();
        if (tid < 128) {
            float pn = sPn[tid] + sPn[128 + tid] + sPn[256 + tid] + sPn[384 + tid];
            float ps = sPs[tid] + sPs[128 + tid] + sPs[256 + tid] + sPs[384 + tid];
            g_pnum[((size_t)(m0 + tid) * HCn + hc) * 16 + q] = pn;
            g_psq [((size_t)(m0 + tid) * HCn + hc) * 16 + q] = ps;
        }
    }
#endif
}

// ---------------- K4: gates, alpha, sgate (one warp per row) ----------------
__global__ void k_gate()
{
    const int row  = blockIdx.x;
    const int lane = threadIdx.x;

    float v = (lane < 16) ? g_vsq[row * 16 + lane] : 0.f;
#if USE_TC
    float hv = (lane < 16) ? g_hsq[row * 16 + lane] : 0.f;
#endif
    #pragma unroll
    for (int q = 16; q > 0; q >>= 1) {
        v += __shfl_down_sync(0xffffffffu, v, q);
#if USE_TC
        hv += __shfl_down_sync(0xffffffffu, hv, q);
#endif
    }
    const float smsq = __shfl_sync(0xffffffffu, v, 0) * (1.f / HIDn);
#if USE_TC
    const float invq = rsqrtf(__shfl_sync(0xffffffffu, hv, 0) * (1.f / HIDn) + EPS_RMS);
#else
    const float invq = g_invq[row];
#endif

    const int g = lane >> 3, j = lane & 7;
    const float* pn = g_pnum + ((size_t)row * HCn + g) * 16;
    const float* pq = g_psq  + ((size_t)row * HCn + g) * 16;
    float num = pn[j] + pn[j + 8];
    float sq  = pq[j] + pq[j + 8];
    #pragma unroll
    for (int q = 4; q > 0; q >>= 1) {
        num += __shfl_down_sync(0xffffffffu, num, q, 8);
        sq  += __shfl_down_sync(0xffffffffu, sq,  q, 8);
    }
    float gate = 0.f;
    if (j == 0) {
        float irk = rsqrtf(sq * (1.f / HIDn) + EPS_RMS);
        float gg  = num * irk * invq * 0.022097086912079608f;   // 1/sqrt(2048)
        float sgn = (gg > 0.f) ? 1.f : ((gg < 0.f) ? -1.f : 0.f);
        float gs  = sgn * sqrtf(fmaxf(fabsf(gg), 1e-6f));
        gate = 1.f / (1.f + __expf(-gs));
        g_alpha[(size_t)row * HCn + g] = gate * rsqrtf(gate * gate * smsq + EPS_SC);
    }
    float sg = __shfl_sync(0xffffffffu, gate, 0) + __shfl_sync(0xffffffffu, gate, 8)
             + __shfl_sync(0xffffffffu, gate, 16) + __shfl_sync(0xffffffffu, gate, 24);
    if (lane == 0) g_sgate[row] = sg;
}

// ---------------- K5: rolling-tap dilated conv + silu + hc-sum --------------
// Thread owns a channel quad + one (t mod 3) phase and marches t += 3 for up
// to SCHUNK outputs. Taps are stride-3, so each step loads ONE new vp float4 +
// ONE alpha float4; the 20 weight loads amortize over the whole chunk.
__global__ void __launch_bounds__(256)
k_out(const float* __restrict__ scw,
      const float* __restrict__ cw,
      float* __restrict__ out)
{
    const int cq = blockIdx.x * 256 + threadIdx.x;   // 0..511 channel quad
    const int c  = cq * 4;
    const int bz = blockIdx.z;                       // 0..5 = b*3 + phase
    const int b  = bz / 3, p = bz % 3;
    const int ns = (Ln - p + 2) / 3;                 // #outputs in this phase
    const int s0 = blockIdx.y * SCHUNK;
    if (s0 >= ns) return;
    const int send = (s0 + SCHUNK < ns) ? s0 + SCHUNK : ns;
    const int rbase = b * Ln;

    // per-thread weights (amortized over the chunk)
    float4 wreg[4][4];
    float  screg[4][4];
    #pragma unroll
    for (int g = 0; g < 4; g++) {
        float4 sw = *(const float4*)(scw + g * HIDn + c);
        screg[g][0] = sw.x; screg[g][1] = sw.y; screg[g][2] = sw.z; screg[g][3] = sw.w;
        #pragma unroll
        for (int j = 0; j < 4; j++)
            wreg[g][j] = *(const float4*)(cw + ((size_t)(g * HIDn + c + j)) * 4);
    }

    // rolling tap window: slot k holds t + 3k - 9 for the current output t
    float v[4][4];
    float al[4][4];
    const int tfirst = p + 3 * s0;
    #pragma unroll
    for (int k = 0; k < 3; k++) {
        const int tt = tfirst + 3 * k - 9;
        if (tt >= 0) {
            float4 vv = *(const float4*)(g_vp + (size_t)(rbase + tt) * HIDn + c);
            float4 aa = *(const float4*)(g_alpha + (size_t)(rbase + tt) * HCn);
            v[k][0] = vv.x; v[k][1] = vv.y; v[k][2] = vv.z; v[k][3] = vv.w;
            al[k][0] = aa.x; al[k][1] = aa.y; al[k][2] = aa.z; al[k][3] = aa.w;
        } else {
            #pragma unroll
            for (int j = 0; j < 4; j++) { v[k][j] = 0.f; al[k][j] = 0.f; }
        }
    }

    #pragma unroll 1
    for (int s = s0; s < send; s++) {
        const int t = p + 3 * s;
        const int r = rbase + t;
        {
            float4 vv = *(const float4*)(g_vp + (size_t)r * HIDn + c);
            float4 aa = *(const float4*)(g_alpha + (size_t)r * HCn);
            v[3][0] = vv.x; v[3][1] = vv.y; v[3][2] = vv.z; v[3][3] = vv.w;
            al[3][0] = aa.x; al[3][1] = aa.y; al[3][2] = aa.z; al[3][3] = aa.w;
        }
        const float sgate = g_sgate[r];
        float o[4];
        #pragma unroll
        for (int j = 0; j < 4; j++) o[j] = sgate * v[3][j];

        #pragma unroll
        for (int g = 0; g < 4; g++) {
            #pragma unroll
            for (int j = 0; j < 4; j++) {
                const float4 w = wreg[g][j];
                float y = w.x * al[0][g] * v[0][j]
                        + w.y * al[1][g] * v[1][j]
                        + w.z * al[2][g] * v[2][j]
                        + w.w * al[3][g] * v[3][j];
                y *= screg[g][j];
                o[j] += y / (1.f + __expf(-y));
            }
        }
        *(float4*)(out + (size_t)r * HIDn + c) = make_float4(o[0], o[1], o[2], o[3]);

        #pragma unroll
        for (int k = 0; k < 3; k++)
            #pragma unroll
            for (int j = 0; j < 4; j++) { v[k][j] = v[k + 1][j]; al[k][j] = al[k + 1][j]; }
    }
}

// ---------------- host: tensormap construction + launch ----------------
typedef CUresult (*PFN_tmEncode)(
    CUtensorMap*, CUtensorMapDataType, cuuint32_t, void*,
    const cuuint64_t*, const cuuint64_t*, const cuuint32_t*, const cuuint32_t*,
    CUtensorMapInterleave, CUtensorMapSwizzle, CUtensorMapL2promotion,
    CUtensorMapFloatOOBfill);

static void encode_map(PFN_tmEncode fn, CUtensorMap* tm, void* base, unsigned rows)
{
    cuuint64_t dims[2]    = {2048ull, (cuuint64_t)rows};  // bytes per row, rows
    cuuint64_t strides[1] = {2048ull};
    cuuint32_t box[2]     = {128u, 128u};
    cuuint32_t es[2]      = {1u, 1u};
    fn(tm, CU_TENSOR_MAP_DATA_TYPE_UINT8, 2, base, dims, strides, box, es,
       CU_TENSOR_MAP_INTERLEAVE_NONE, CU_TENSOR_MAP_SWIZZLE_128B,
       CU_TENSOR_MAP_L2_PROMOTION_L2_128B, CU_TENSOR_MAP_FLOAT_OOB_FILL_NONE);
}

extern "C" void kernel_launch(void* const* d_in, const int* in_sizes, int n_in,
                              void* d_out, int out_size)
{
    (void)in_sizes; (void)n_in; (void)out_size;
    const float* hid = (const float*)d_in[0];
    const void*  ids = d_in[1];
    const float* tab = (const float*)d_in[2];
    const float* vw  = (const float*)d_in[3];
    const float* vb  = (const float*)d_in[4];
    const float* kw  = (const float*)d_in[5];
    const float* kb  = (const float*)d_in[6];
    const float* n1  = (const float*)d_in[7];
    const float* n2  = (const float*)d_in[8];
    const float* scw = (const float*)d_in[9];
    const float* cw  = (const float*)d_in[10];
    float* out = (float*)d_out;

    PFN_tmEncode fn = nullptr;
    cudaDriverEntryPointQueryResult qres;
    cudaGetDriverEntryPointByVersion("cuTensorMapEncodeTiled", (void**)&fn,
                                     12000, cudaEnableDefault, &qres);
    void *pAh, *pAl, *pBh, *pBl;
    cudaGetSymbolAddress(&pAh, g_embh);
    cudaGetSymbolAddress(&pAl, g_embl);
    cudaGetSymbolAddress(&pBh, g_wth);
    cudaGetSymbolAddress(&pBl, g_wtl);
    CUtensorMap tmAh{}, tmAl{}, tmBh{}, tmBl{};
    if (fn) {
        encode_map(fn, &tmAh, pAh, Mn);
        encode_map(fn, &tmAl, pAl, Mn);
        encode_map(fn, &tmBh, pBh, NTOT);
        encode_map(fn, &tmBl, pBl, NTOT);
    }

    int ccM = 0, ccm = 0, dev = 0;
    cudaGetDevice(&dev);
    cudaDeviceGetAttribute(&ccM, cudaDevAttrComputeCapabilityMajor, dev);
    cudaDeviceGetAttribute(&ccm, cudaDevAttrComputeCapabilityMinor, dev);
    const bool isSm103 = (ccM == 10 && ccm == 3);

    cudaFuncSetAttribute(k_tcgemm,  cudaFuncAttributeMaxDynamicSharedMemorySize, GSMEM);
    cudaFuncSetAttribute(k_gemm_fb, cudaFuncAttributeMaxDynamicSharedMemorySize, FB_SMEM);

    k_prep<<<Mn + (NTOT / 64) * (ENGn / 64), 256>>>(ids, tab, hid, vw, kw);
    if (!isSm103)
        k_gemm_fb<<<dim3(80, 64), 256, FB_SMEM>>>(vb, kb, n1, n2, hid);
    k_tcgemm<<<dim3(64, 20), 256, GSMEM>>>(tmAh, tmAl, tmBh, tmBl,
                                           vb, kb, n1, n2, hid);
    k_gate<<<Mn, 32>>>();
    {
        const int nchunks = ((Ln + 2) / 3 + SCHUNK - 1) / SCHUNK;   // 43
        k_out<<<dim3(2, nchunks, 2 * 3), 256>>>(scw, cw, out);
    }
}

// round 16
// speedup vs baseline: 1.4713x; 1.1432x over previous
#include <cuda_runtime.h>
#include <cuda.h>
#include <cuda_bf16.h>
#include <cstdint>

#define Bn 2
#define Ln 4096
#define Mn (Bn*Ln)          // 8192 rows
#define HIDn 2048
#define ENGn 1024
#define NHEADn 16
#define VOCABn 129280
#define HCn 4
#define NTOT 10240          // 2048 value cols + 4*2048 key cols
#define SCHUNK 16           // k_out: outputs per thread (t stride 3)
#define EPS_RMS 1.1920929e-07f
#define EPS_SC  1e-5f

#if defined(__CUDA_ARCH__) && (__CUDA_ARCH__ == 1030) && defined(__CUDA_ARCH_FEAT_SM103_ALL)
#define USE_TC 1
#else
#define USE_TC 0
#endif

// ---------------- scratch (device globals: allocation-free) ----------------
__device__ __nv_bfloat16 g_embh[(size_t)Mn * ENGn];
__device__ __nv_bfloat16 g_embl[(size_t)Mn * ENGn];
__device__ __nv_bfloat16 g_wth [(size_t)NTOT * ENGn];  // W^T hi (keys hc-interleaved)
__device__ __nv_bfloat16 g_wtl [(size_t)NTOT * ENGn];  // W^T lo (key rows stay zero)
__device__ float g_vp [(size_t)Mn * HIDn];
__device__ float g_invq[Mn];                           // used by non-TC path only
__device__ float g_hsq [Mn * 16];                      // TC path: hid^2 partials
__device__ float g_vsq [Mn * 16];
__device__ float g_pnum[Mn * HCn * 16];
__device__ float g_psq [Mn * HCn * 16];
__device__ float g_alpha[Mn * HCn];
__device__ float g_sgate[Mn];

__device__ __forceinline__ uint32_t sm2u(const void* p) {
    return (uint32_t)__cvta_generic_to_shared(p);
}

// ---------------- K1: fused gather (+rms on non-TC) and weight transpose ----
__global__ void k_prep(const void* __restrict__ ids_raw,
                       const float* __restrict__ tab,
                       const float* __restrict__ hid,
                       const float* __restrict__ vw,
                       const float* __restrict__ kw)
{
    __shared__ float ts[64][65];
    const int tid = threadIdx.x;

    if (blockIdx.x < Mn) {
        // ---------------- gather ----------------
        const int row = blockIdx.x;
        int* sid = (int*)&ts[0][0];

        if (tid == 0) {
            const long long* p64 = (const long long*)ids_raw;
            bool is64 = true;
            #pragma unroll
            for (int i = 0; i < 8; i++) {
                long long v = p64[i];
                if (v < 0 || v >= (long long)VOCABn) { is64 = false; break; }
            }
            if (is64) {
                const long long* p = p64 + (size_t)row * NHEADn;
                for (int h = 0; h < NHEADn; h++) sid[h] = (int)p[h];
            } else {
                const int* p = ((const int*)ids_raw) + (size_t)row * NHEADn;
                for (int h = 0; h < NHEADn; h++) sid[h] = p[h];
            }
        }
        __syncthreads();

        #pragma unroll
        for (int e = tid; e < ENGn; e += 256) {
            int h = e >> 6, d = e & 63;
            float v = tab[((size_t)h * VOCABn + (size_t)sid[h]) * 64 + d];
            __nv_bfloat16 hi = __float2bfloat16(v);
            __nv_bfloat16 lo = __float2bfloat16(v - __bfloat162float(hi));
            g_embh[(size_t)row * ENGn + e] = hi;
            g_embl[(size_t)row * ENGn + e] = lo;
        }

#if !USE_TC
        float* sbuf = (float*)&ts[1][0];
        float s = 0.f;
        const float* hr = hid + (size_t)row * HIDn;
        for (int i = tid; i < HIDn; i += 256) { float v = hr[i]; s += v * v; }
        int lane = tid & 31, wid = tid >> 5;
        #pragma unroll
        for (int q = 16; q > 0; q >>= 1) s += __shfl_down_sync(0xffffffffu, s, q);
        if (lane == 0) sbuf[wid] = s;
        __syncthreads();
        if (wid == 0) {
            s = (lane < 8) ? sbuf[lane] : 0.f;
            #pragma unroll
            for (int q = 4; q > 0; q >>= 1) s += __shfl_down_sync(0xffffffffu, s, q);
            if (lane == 0) g_invq[row] = rsqrtf(s * (1.f / HIDn) + EPS_RMS);
        }
#else
        (void)hid;
#endif
    } else {
        // ---------------- weight transpose ----------------
        const int wb = blockIdx.x - Mn;
        const int n0 = (wb % 160) * 64;
        const int k0 = (wb / 160) * 64;
        const int s  = n0 >> 11;
        const float* W = (s == 0) ? vw : kw + (size_t)(s - 1) * ENGn * HIDn;
        const int col0 = n0 & 2047;
        const int tx  = tid & 63;
        const int ty4 = tid >> 6;

        #pragma unroll
        for (int i = 0; i < 16; i++) {
            int kk = ty4 + i * 4;
            ts[kk][tx] = W[(size_t)(k0 + kk) * HIDn + col0 + tx];
        }
        __syncthreads();
        #pragma unroll
        for (int i = 0; i < 16; i++) {
            int nn = ty4 + i * 4;
            float v = ts[tx][nn];
            __nv_bfloat16 hi = __float2bfloat16(v);
            if (s == 0) {
                int orow = n0 + nn;
                size_t o = (size_t)orow * ENGn + k0 + tx;
                g_wth[o] = hi;
                g_wtl[o] = __float2bfloat16(v - __bfloat162float(hi));
            } else {
                int d = col0 + nn;
                int orow = 2048 + ((d >> 7) << 9) + ((s - 1) << 7) + (d & 127);
                g_wth[(size_t)orow * ENGn + k0 + tx] = hi;   // lo stays zero
            }
        }
    }
}

// ================= tcgen05 path (sm_103a feature target) =====================
// cluster pair computes D[256 M, 512 N] over K=1024; 16 kchunks of 64.
// value tiles (nsup<4): 3-term bf16x3. key tiles: pure bf16 (AhBh only).
#define STAGE_B 98304
#define GSMEM   (1024 + 2 * STAGE_B)

#if USE_TC
__device__ __forceinline__ uint64_t mk_desc(uint32_t addr) {
    return 0x4000404000010000ull | (uint64_t)((addr >> 4) & 0x3FFF);
}
__device__ __forceinline__ void mbar_wait(uint32_t a, int ph) {
    asm volatile(
        "{\n\t.reg .pred P;\n\t"
        "W_%=:\n\t"
        "mbarrier.try_wait.parity.acquire.cluster.shared::cta.b64 P, [%0], %1, 0x989680;\n\t"
        "@P bra.uni D_%=;\n\t"
        "bra.uni W_%=;\n\t"
        "D_%=:\n\t}"
        :: "r"(a), "r"(ph) : "memory");
}
__device__ __forceinline__ void remote_arrive(uint32_t a) {
    uint32_t zero = 0;
    asm volatile(
        "{\n\t.reg .b32 ra;\n\t"
        "mapa.shared::cluster.u32 ra, %0, %1;\n\t"
        "mbarrier.arrive.shared::cluster.b64 _, [ra];\n\t}"
        :: "r"(a), "r"(zero) : "memory");
}
__device__ __forceinline__ void mma_f16_cg2(uint32_t d, uint64_t da, uint64_t db,
                                            uint32_t idesc, bool en) {
    uint32_t e = en ? 1u : 0u, z = 0u;
    asm volatile(
        "{\n\t.reg .pred p;\n\t"
        "setp.ne.u32 p, %5, 0;\n\t"
        "tcgen05.mma.cta_group::2.kind::f16 [%0], %1, %2, %3, "
        "{%4, %4, %4, %4, %4, %4, %4, %4}, p;\n\t}"
        :: "r"(d), "l"(da), "l"(db), "r"(idesc), "r"(z), "r"(e) : "memory");
}
#define TC_LD32(r, a) \
    asm volatile("tcgen05.ld.sync.aligned.32x32b.x32.b32 " \
        "{%0, %1, %2, %3, %4, %5, %6, %7, %8, %9, %10, %11, %12, %13, %14, %15, " \
        "%16, %17, %18, %19, %20, %21, %22, %23, %24, %25, %26, %27, %28, %29, %30, %31}, [%32];" \
        : "=r"((r)[0]), "=r"((r)[1]), "=r"((r)[2]), "=r"((r)[3]), \
          "=r"((r)[4]), "=r"((r)[5]), "=r"((r)[6]), "=r"((r)[7]), \
          "=r"((r)[8]), "=r"((r)[9]), "=r"((r)[10]), "=r"((r)[11]), \
          "=r"((r)[12]), "=r"((r)[13]), "=r"((r)[14]), "=r"((r)[15]), \
          "=r"((r)[16]), "=r"((r)[17]), "=r"((r)[18]), "=r"((r)[19]), \
          "=r"((r)[20]), "=r"((r)[21]), "=r"((r)[22]), "=r"((r)[23]), \
          "=r"((r)[24]), "=r"((r)[25]), "=r"((r)[26]), "=r"((r)[27]), \
          "=r"((r)[28]), "=r"((r)[29]), "=r"((r)[30]), "=r"((r)[31]) \
        : "r"(a))
#define TC_WAIT_LD() asm volatile("tcgen05.wait::ld.sync.aligned;" ::: "memory")
#define TMA2D(dst, map, x, y, bar) \
    asm volatile("cp.async.bulk.tensor.2d.shared::cta.global.tile" \
                 ".mbarrier::complete_tx::bytes [%0], [%1, {%2, %3}], [%4];" \
                 :: "r"(dst), "l"(map), "r"(x), "r"(y), "r"(bar) : "memory")
#define MBAR_EXPECT(bar, bytes) \
    asm volatile("mbarrier.arrive.expect_tx.shared.b64 _, [%0], %1;" \
                 :: "r"(bar), "r"(bytes) : "memory")
#endif

__global__ void __launch_bounds__(256, 1) __cluster_dims__(2, 1, 1)
k_tcgemm(const __grid_constant__ CUtensorMap tmAh,
         const __grid_constant__ CUtensorMap tmAl,
         const __grid_constant__ CUtensorMap tmBh,
         const __grid_constant__ CUtensorMap tmBl,
         const float* __restrict__ vb, const float* __restrict__ kb,
         const float* __restrict__ n1, const float* __restrict__ n2,
         const float* __restrict__ hid)
{
#if !USE_TC
    (void)vb; (void)kb; (void)n1; (void)n2; (void)hid;
    return;
#else
    extern __shared__ char sm[];
    const int tid  = threadIdx.x;
    const int rank = blockIdx.x & 1;
    const int m0   = (blockIdx.x >> 1) * 256;
    const int nsup = blockIdx.y;                       // 0..19
    const bool isKey = (nsup >= 4);
    const uint32_t sb = sm2u(sm);
    const uint32_t mb_fullA = sb + 16;
    const uint32_t mb_fullB = sb + 32;
    const uint32_t mb_relA  = sb + 48;
    const uint32_t mb_relB  = sb + 64;
    const uint32_t mb_done  = sb + 80;

    if (tid == 0) {
        #pragma unroll
        for (int s = 0; s < 2; s++) {
            asm volatile("mbarrier.init.shared.b64 [%0], 1;" :: "r"(mb_fullA + s * 8) : "memory");
            asm volatile("mbarrier.init.shared.b64 [%0], 1;" :: "r"(mb_fullB + s * 8) : "memory");
            asm volatile("mbarrier.init.shared.b64 [%0], 1;" :: "r"(mb_relA  + s * 8) : "memory");
            asm volatile("mbarrier.init.shared.b64 [%0], 1;" :: "r"(mb_relB  + s * 8) : "memory");
            asm volatile("mbarrier.init.shared.b64 [%0], 1;" :: "r"(mb_done  + s * 8) : "memory");
        }
    }
    if (tid < 32) {
        asm volatile("tcgen05.alloc.cta_group::2.sync.aligned.shared::cta.b32 [%0], 512;"
                     :: "r"(sb) : "memory");
    }
    __syncthreads();
    uint32_t tmem;
    asm volatile("ld.shared.b32 %0, [%1];" : "=r"(tmem) : "r"(sb));
    asm volatile("barrier.cluster.arrive.aligned;" ::: "memory");
    asm volatile("barrier.cluster.wait.aligned;"   ::: "memory");

    const uint32_t idesc = (1u << 4) | (1u << 7) | (1u << 10)
                         | ((256u / 8) << 17) | ((256u / 16) << 24);

    if (tid == 0) {
        const int ar  = m0 + rank * 128;
        const int br0 = nsup * 512 + rank * 128;
        const int br1 = nsup * 512 + 256 + rank * 128;
        int fphA[2] = {0,0}, fphB[2] = {0,0};
        int rphA[2] = {0,0}, rphB[2] = {0,0};
        int dph [2] = {0,0};

        auto issue = [&](int kc, int s) {
            const uint32_t d0 = sb + 1024 + s * STAGE_B;
            const int x = kc * 128;
            MBAR_EXPECT(mb_fullA + s * 8, 49152u);
            TMA2D(d0,          &tmAh, x, ar,  mb_fullA + s * 8);
            TMA2D(d0 + 32768,  &tmBh, x, br0, mb_fullA + s * 8);
            TMA2D(d0 + 49152,  &tmBh, x, br1, mb_fullA + s * 8);
            if (!isKey) {
                MBAR_EXPECT(mb_fullB + s * 8, 49152u);
                TMA2D(d0 + 16384,  &tmAl, x, ar,  mb_fullB + s * 8);
                TMA2D(d0 + 65536,  &tmBl, x, br0, mb_fullB + s * 8);
                TMA2D(d0 + 81920,  &tmBl, x, br1, mb_fullB + s * 8);
            }
        };
        auto compute = [&](int kc, int sp) {
            if (rank == 0) {
                mbar_wait(mb_fullA + sp * 8, fphA[sp]); fphA[sp] ^= 1;
                mbar_wait(mb_relA  + sp * 8, rphA[sp]); rphA[sp] ^= 1;
                const uint32_t a = sb + 1024 + sp * STAGE_B;
                const uint64_t dAh = mk_desc(a);
                #pragma unroll
                for (int h = 0; h < 2; h++) {
                    const uint64_t dBh = mk_desc(a + 32768 + h * 16384);
                    const uint32_t dst = tmem + h * 256;
                    #pragma unroll
                    for (int ks = 0; ks < 4; ks++)
                        mma_f16_cg2(dst, dAh + ks * 2, dBh + ks * 2, idesc,
                                    !(kc == 0 && ks == 0));
                }
                if (!isKey) {
                    mbar_wait(mb_fullB + sp * 8, fphB[sp]); fphB[sp] ^= 1;
                    mbar_wait(mb_relB  + sp * 8, rphB[sp]); rphB[sp] ^= 1;
                    const uint64_t dAl = mk_desc(a + 16384);
                    #pragma unroll
                    for (int h = 0; h < 2; h++) {
                        const uint64_t dBh = mk_desc(a + 32768 + h * 16384);
                        const uint64_t dBl = mk_desc(a + 65536 + h * 16384);
                        const uint32_t dst = tmem + h * 256;
                        #pragma unroll
                        for (int ks = 0; ks < 4; ks++) {
                            mma_f16_cg2(dst, dAh + ks * 2, dBl + ks * 2, idesc, true);
                            mma_f16_cg2(dst, dAl + ks * 2, dBh + ks * 2, idesc, true);
                        }
                    }
                }
                asm volatile(
                    "tcgen05.commit.cta_group::2.mbarrier::arrive::one.shared::cluster"
                    ".multicast::cluster.b64 [%0], %1;"
                    :: "r"(mb_done + sp * 8), "h"((uint16_t)3) : "memory");
            } else {
                mbar_wait(mb_fullA + sp * 8, fphA[sp]); fphA[sp] ^= 1;
                remote_arrive(mb_relA + sp * 8);
                if (!isKey) {
                    mbar_wait(mb_fullB + sp * 8, fphB[sp]); fphB[sp] ^= 1;
                    remote_arrive(mb_relB + sp * 8);
                }
            }
        };

        #pragma unroll 1
        for (int kc = 0; kc < 16; kc++) {
            const int s = kc & 1;
            if (kc >= 2) { mbar_wait(mb_done + s * 8, dph[s]); dph[s] ^= 1; }
            issue(kc, s);
            if (kc >= 1) compute(kc - 1, s ^ 1);
        }
        compute(15, 1);
        mbar_wait(mb_done + 8, dph[1]);
    }
    __syncthreads();
    asm volatile("tcgen05.fence::after_thread_sync;" ::: "memory");

    // -------- coalesced epilogue (per-warp 32x33 SMEM transpose tile) --------
    const int w = tid >> 5, lane = tid & 31;
    const int h  = w >> 2;
    const int rg = w & 3;
    const int r0 = m0 + rank * 128 + rg * 32;
    const int r  = r0 + lane;
    float* tile = (float*)(sm + 1024) + w * (32 * 33);

    if (nsup < 4) {
        float vsq = 0.f;
        const int nb0 = nsup * 512 + h * 256;
        #pragma unroll
        for (int q = 0; q < 8; q++) {
            uint32_t d[32];
            TC_LD32(d, tmem + h * 256 + q * 32);
            TC_WAIT_LD();
            const int nb = nb0 + q * 32;
            #pragma unroll
            for (int c = 0; c < 32; c++) {
                float o = __uint_as_float(d[c]) + __ldg(vb + nb + c);
                vsq = fmaf(o, o, vsq);
                tile[lane * 33 + c] = o;
            }
            __syncwarp();
            #pragma unroll
            for (int rr = 0; rr < 32; rr++)
                g_vp[(size_t)(r0 + rr) * HIDn + nb + lane] = tile[rr * 33 + lane];
            __syncwarp();
        }
        g_vsq[r * 16 + nsup * 2 + h] = vsq;
    } else {
        const int q = nsup - 4;
        float pn[2] = {0.f, 0.f}, ps[2] = {0.f, 0.f};
        float hsq = 0.f;
        #pragma unroll
        for (int dq = 0; dq < 4; dq++) {
            const int dwin = q * 128 + dq * 32;
            #pragma unroll
            for (int rr = 0; rr < 32; rr++)
                tile[rr * 33 + lane] = __ldg(hid + (size_t)(r0 + rr) * HIDn + dwin + lane);
            __syncwarp();
            if (h == 0) {
                #pragma unroll
                for (int c = 0; c < 32; c++) {
                    float t = tile[lane * 33 + c];
                    hsq = fmaf(t, t, hsq);
                }
            }
            #pragma unroll
            for (int hcl = 0; hcl < 2; hcl++) {
                const int hc = h * 2 + hcl;
                uint32_t d[32];
                TC_LD32(d, tmem + h * 256 + hcl * 128 + dq * 32);
                TC_WAIT_LD();
                const int nb = hc * HIDn + dwin;
                #pragma unroll
                for (int c = 0; c < 32; c++) {
                    float kv = __uint_as_float(d[c]) + __ldg(kb + nb + c);
                    float w12 = __ldg(n1 + nb + c) * __ldg(n2 + nb + c);
                    pn[hcl] = fmaf(kv * w12, tile[lane * 33 + c], pn[hcl]);
                    ps[hcl] = fmaf(kv, kv, ps[hcl]);
                }
            }
            __syncwarp();
        }
        if (h == 0) g_hsq[r * 16 + q] = hsq;
        #pragma unroll
        for (int hcl = 0; hcl < 2; hcl++) {
            const int hc = h * 2 + hcl;
            g_pnum[((size_t)r * HCn + hc) * 16 + q] = pn[hcl];
            g_psq [((size_t)r * HCn + hc) * 16 + q] = ps[hcl];
        }
    }

    __syncthreads();
    if (tid < 32) {
        asm volatile("tcgen05.relinquish_alloc_permit.cta_group::2.sync.aligned;");
        asm volatile("tcgen05.dealloc.cta_group::2.sync.aligned.b32 %0, 512;" :: "r"(tmem));
    }
    asm volatile("barrier.cluster.arrive.aligned;" ::: "memory");
    asm volatile("barrier.cluster.wait.aligned;"   ::: "memory");
#endif
}

// ============ fallback: mma.sync bf16x3 pipelined GEMM (plain sm_103) ========
#define FB_STAGE 40960
#define FB_SMEM  (3 * FB_STAGE)

#define LDSM4(r, addr) \
    asm volatile("ldmatrix.sync.aligned.m8n8.x4.shared.b16 {%0,%1,%2,%3}, [%4];" \
        : "=r"((r)[0]), "=r"((r)[1]), "=r"((r)[2]), "=r"((r)[3]) : "r"(addr))

#define MMA16816(c, a, b) \
    asm volatile("mma.sync.aligned.m16n8k16.row.col.f32.bf16.bf16.f32 " \
        "{%0,%1,%2,%3}, {%4,%5,%6,%7}, {%8,%9}, {%0,%1,%2,%3};" \
        : "+f"((c)[0]), "+f"((c)[1]), "+f"((c)[2]), "+f"((c)[3]) \
        : "r"((a)[0]), "r"((a)[1]), "r"((a)[2]), "r"((a)[3]), \
          "r"((b)[0]), "r"((b)[1]))

__global__ void __launch_bounds__(256, 1)
k_gemm_fb(const float* __restrict__ vb, const float* __restrict__ kb,
          const float* __restrict__ n1, const float* __restrict__ n2,
          const float* __restrict__ hid)
{
#if USE_TC
    (void)vb; (void)kb; (void)n1; (void)n2; (void)hid;
    return;
#else
    extern __shared__ char smem[];
    const uint32_t sb = sm2u(smem);
    const int tid = threadIdx.x;
    const int ntile = blockIdx.x;
    const int m0 = blockIdx.y * 128;
    const int n0 = ntile * 128;

    const char* gA_h = (const char*)(g_embh + (size_t)m0 * ENGn);
    const char* gA_l = (const char*)(g_embl + (size_t)m0 * ENGn);
    const char* gB_h = (const char*)(g_wth + (size_t)n0 * ENGn);
    const char* gB_l = (const char*)(g_wtl + (size_t)n0 * ENGn);

    const int ch = tid & 3;
    auto load_stage = [&](int s, int kc) {
        #pragma unroll
        for (int i = 0; i < 8; i++) {
            const int tsel = i >> 1;
            const int row = (((i & 1) << 8) + tid) >> 2;
            const char* src = (tsel == 0 ? gA_h : tsel == 1 ? gA_l :
                               tsel == 2 ? gB_h : gB_l)
                              + (size_t)row * 2048 + kc * 64 + ch * 16;
            uint32_t d = sb + s * FB_STAGE + tsel * 10240 + row * 80 + ch * 16;
            asm volatile("cp.async.cg.shared.global [%0], [%1], 16;"
                         :: "r"(d), "l"(src));
        }
        asm volatile("cp.async.commit_group;" ::: "memory");
    };

    load_stage(0, 0);
    load_stage(1, 1);

    float acc[4][4][4];
    #pragma unroll
    for (int i = 0; i < 4; i++)
        #pragma unroll
        for (int j = 0; j < 4; j++)
            #pragma unroll
            for (int q = 0; q < 4; q++) acc[i][j][q] = 0.f;

    const int lane = tid & 31, w = tid >> 5;
    const int wm = w >> 2, wn = w & 3;
    const uint32_t aRow   = wm * 64 + (lane & 15);
    const uint32_t aChunk = (lane >> 4) * 16;
    const int g = lane >> 3;
    const uint32_t bRow   = wn * 32 + ((g >> 1) & 1) * 8 + (lane & 7);
    const uint32_t bChunk = (g & 1) * 16;

    for (int kt = 0; kt < 32; kt++) {
        if (kt + 2 < 32) load_stage((kt + 2) % 3, kt + 2);
        else asm volatile("cp.async.commit_group;" ::: "memory");
        asm volatile("cp.async.wait_group 2;" ::: "memory");
        __syncthreads();

        const uint32_t st = sb + (kt % 3) * FB_STAGE;
        #pragma unroll
        for (int hh = 0; hh < 2; hh++) {
            uint32_t ah[4][4], al[4][4], bh[4][2], bl[4][2];
            #pragma unroll
            for (int mi = 0; mi < 4; mi++) {
                uint32_t ra = st + (aRow + mi * 16) * 80 + hh * 32 + aChunk;
                LDSM4(ah[mi], ra);
                LDSM4(al[mi], ra + 10240);
            }
            #pragma unroll
            for (int p = 0; p < 2; p++) {
                uint32_t rb = st + 20480 + (bRow + p * 16) * 80 + hh * 32 + bChunk;
                uint32_t r[4];
                LDSM4(r, rb);
                bh[2*p][0] = r[0]; bh[2*p][1] = r[1];
                bh[2*p+1][0] = r[2]; bh[2*p+1][1] = r[3];
                LDSM4(r, rb + 10240);
                bl[2*p][0] = r[0]; bl[2*p][1] = r[1];
                bl[2*p+1][0] = r[2]; bl[2*p+1][1] = r[3];
            }
            #pragma unroll
            for (int mi = 0; mi < 4; mi++)
                #pragma unroll
                for (int ni = 0; ni < 4; ni++) {
                    MMA16816(acc[mi][ni], ah[mi], bh[ni]);
                    MMA16816(acc[mi][ni], ah[mi], bl[ni]);
                    MMA16816(acc[mi][ni], al[mi], bh[ni]);
                }
        }
        __syncthreads();
    }

    float* sRed = (float*)smem;
    const int tq = lane & 3, rq = lane >> 2;

    if (ntile < 16) {
        #pragma unroll
        for (int mi = 0; mi < 4; mi++) {
            float vs0 = 0.f, vs1 = 0.f;
            const int r0 = m0 + wm * 64 + mi * 16 + rq;
            #pragma unroll
            for (int ni = 0; ni < 4; ni++) {
                const int n = n0 + wn * 32 + ni * 8 + tq * 2;
                float b0 = vb[n], b1 = vb[n + 1];
                float v00 = acc[mi][ni][0] + b0, v01 = acc[mi][ni][1] + b1;
                float v10 = acc[mi][ni][2] + b0, v11 = acc[mi][ni][3] + b1;
                *(float2*)(g_vp + (size_t)r0 * HIDn + n)       = make_float2(v00, v01);
                *(float2*)(g_vp + (size_t)(r0 + 8) * HIDn + n) = make_float2(v10, v11);
                vs0 += v00 * v00 + v01 * v01;
                vs1 += v10 * v10 + v11 * v11;
            }
            vs0 += __shfl_xor_sync(~0u, vs0, 1); vs0 += __shfl_xor_sync(~0u, vs0, 2);
            vs1 += __shfl_xor_sync(~0u, vs1, 1); vs1 += __shfl_xor_sync(~0u, vs1, 2);
            if (tq == 0) {
                int lr = wm * 64 + mi * 16 + rq;
                sRed[wn * 128 + lr]     = vs0;
                sRed[wn * 128 + lr + 8] = vs1;
            }
        }
        __syncthreads();
        if (tid < 128) {
            float s = sRed[tid] + sRed[128 + tid] + sRed[256 + tid] + sRed[384 + tid];
            g_vsq[(m0 + tid) * 16 + ntile] = s;
        }
    } else {
        const int kbase = (ntile - 16) * 128;
        const int hc = (kbase >> 7) & 3;
        const int q  = kbase >> 9;
        float* sPn = sRed;
        float* sPs = sRed + 512;
        #pragma unroll
        for (int mi = 0; mi < 4; mi++) {
            float pn0 = 0.f, ps0 = 0.f, pn1 = 0.f, ps1 = 0.f;
            const int r0 = m0 + wm * 64 + mi * 16 + rq;
            #pragma unroll
            for (int ni = 0; ni < 4; ni++) {
                const int cl = wn * 32 + ni * 8 + tq * 2;
                const int dd = q * 128 + cl;
                const int nb = hc * HIDn + dd;
                float b0 = kb[nb], b1 = kb[nb + 1];
                float w0 = n1[nb] * n2[nb], w1 = n1[nb + 1] * n2[nb + 1];
                float k00 = acc[mi][ni][0] + b0, k01 = acc[mi][ni][1] + b1;
                float k10 = acc[mi][ni][2] + b0, k11 = acc[mi][ni][3] + b1;
                const float* h0 = hid + (size_t)r0 * HIDn + dd;
                const float* h1 = hid + (size_t)(r0 + 8) * HIDn + dd;
                pn0 += k00 * w0 * h0[0] + k01 * w1 * h0[1];
                ps0 += k00 * k00 + k01 * k01;
                pn1 += k10 * w0 * h1[0] + k11 * w1 * h1[1];
                ps1 += k10 * k10 + k11 * k11;
            }
            pn0 += __shfl_xor_sync(~0u, pn0, 1); pn0 += __shfl_xor_sync(~0u, pn0, 2);
            ps0 += __shfl_xor_sync(~0u, ps0, 1); ps0 += __shfl_xor_sync(~0u, ps0, 2);
            pn1 += __shfl_xor_sync(~0u, pn1, 1); pn1 += __shfl_xor_sync(~0u, pn1, 2);
            ps1 += __shfl_xor_sync(~0u, ps1, 1); ps1 += __shfl_xor_sync(~0u, ps1, 2);
            if (tq == 0) {
                int lr = wm * 64 + mi * 16 + rq;
                sPn[wn * 128 + lr]     = pn0;  sPn[wn * 128 + lr + 8] = pn1;
                sPs[wn * 128 + lr]     = ps0;  sPs[wn * 128 + lr + 8] = ps1;
            }
        }
        __syncthreads();
        if (tid < 128) {
            float pn = sPn[tid] + sPn[128 + tid] + sPn[256 + tid] + sPn[384 + tid];
            float ps = sPs[tid] + sPs[128 + tid] + sPs[256 + tid] + sPs[384 + tid];
            g_pnum[((size_t)(m0 + tid) * HCn + hc) * 16 + q] = pn;
            g_psq [((size_t)(m0 + tid) * HCn + hc) * 16 + q] = ps;
        }
    }
#endif
}

// ---------------- K4: gates, alpha, sgate (one warp per row) ----------------
__global__ void k_gate()
{
    const int row  = blockIdx.x;
    const int lane = threadIdx.x;

    float v = (lane < 16) ? g_vsq[row * 16 + lane] : 0.f;
#if USE_TC
    float hv = (lane < 16) ? g_hsq[row * 16 + lane] : 0.f;
#endif
    #pragma unroll
    for (int q = 16; q > 0; q >>= 1) {
        v += __shfl_down_sync(0xffffffffu, v, q);
#if USE_TC
        hv += __shfl_down_sync(0xffffffffu, hv, q);
#endif
    }
    const float smsq = __shfl_sync(0xffffffffu, v, 0) * (1.f / HIDn);
#if USE_TC
    const float invq = rsqrtf(__shfl_sync(0xffffffffu, hv, 0) * (1.f / HIDn) + EPS_RMS);
#else
    const float invq = g_invq[row];
#endif

    const int g = lane >> 3, j = lane & 7;
    const float* pn = g_pnum + ((size_t)row * HCn + g) * 16;
    const float* pq = g_psq  + ((size_t)row * HCn + g) * 16;
    float num = pn[j] + pn[j + 8];
    float sq  = pq[j] + pq[j + 8];
    #pragma unroll
    for (int q = 4; q > 0; q >>= 1) {
        num += __shfl_down_sync(0xffffffffu, num, q, 8);
        sq  += __shfl_down_sync(0xffffffffu, sq,  q, 8);
    }
    float gate = 0.f;
    if (j == 0) {
        float irk = rsqrtf(sq * (1.f / HIDn) + EPS_RMS);
        float gg  = num * irk * invq * 0.022097086912079608f;   // 1/sqrt(2048)
        float sgn = (gg > 0.f) ? 1.f : ((gg < 0.f) ? -1.f : 0.f);
        float gs  = sgn * sqrtf(fmaxf(fabsf(gg), 1e-6f));
        gate = 1.f / (1.f + __expf(-gs));
        g_alpha[(size_t)row * HCn + g] = gate * rsqrtf(gate * gate * smsq + EPS_SC);
    }
    float sg = __shfl_sync(0xffffffffu, gate, 0) + __shfl_sync(0xffffffffu, gate, 8)
             + __shfl_sync(0xffffffffu, gate, 16) + __shfl_sync(0xffffffffu, gate, 24);
    if (lane == 0) g_sgate[row] = sg;
}

// ---------------- K5: rolling-tap dilated conv + silu + hc-sum --------------
// Thread owns a channel quad + one (t mod 3) phase and marches t += 3.
// Taps are stride-3: each step loads ONE new vp float4 + ONE alpha float4;
// weight loads amortize over the chunk. Fast-div silu (RCP+MUL).
__global__ void __launch_bounds__(256)
k_out(const float* __restrict__ scw,
      const float* __restrict__ cw,
      float* __restrict__ out)
{
    const int cq = blockIdx.x * 256 + threadIdx.x;   // 0..511 channel quad
    const int c  = cq * 4;
    const int bz = blockIdx.z;                       // 0..5 = b*3 + phase
    const int b  = bz / 3, p = bz % 3;
    const int ns = (Ln - p + 2) / 3;                 // #outputs in this phase
    const int s0 = blockIdx.y * SCHUNK;
    if (s0 >= ns) return;
    const int send = (s0 + SCHUNK < ns) ? s0 + SCHUNK : ns;
    const int rbase = b * Ln;

    // per-thread weights (amortized over the chunk)
    float4 wreg[4][4];
    float  screg[4][4];
    #pragma unroll
    for (int g = 0; g < 4; g++) {
        float4 sw = *(const float4*)(scw + g * HIDn + c);
        screg[g][0] = sw.x; screg[g][1] = sw.y; screg[g][2] = sw.z; screg[g][3] = sw.w;
        #pragma unroll
        for (int j = 0; j < 4; j++)
            wreg[g][j] = *(const float4*)(cw + ((size_t)(g * HIDn + c + j)) * 4);
    }

    // rolling tap window: slot k holds t + 3k - 9 for the current output t
    float v[4][4];
    float al[4][4];
    const int tfirst = p + 3 * s0;
    #pragma unroll
    for (int k = 0; k < 3; k++) {
        const int tt = tfirst + 3 * k - 9;
        if (tt >= 0) {
            float4 vv = *(const float4*)(g_vp + (size_t)(rbase + tt) * HIDn + c);
            float4 aa = *(const float4*)(g_alpha + (size_t)(rbase + tt) * HCn);
            v[k][0] = vv.x; v[k][1] = vv.y; v[k][2] = vv.z; v[k][3] = vv.w;
            al[k][0] = aa.x; al[k][1] = aa.y; al[k][2] = aa.z; al[k][3] = aa.w;
        } else {
            #pragma unroll
            for (int j = 0; j < 4; j++) { v[k][j] = 0.f; al[k][j] = 0.f; }
        }
    }

    #pragma unroll 4
    for (int s = s0; s < send; s++) {
        const int t = p + 3 * s;
        const int r = rbase + t;
        {
            float4 vv = *(const float4*)(g_vp + (size_t)r * HIDn + c);
            float4 aa = *(const float4*)(g_alpha + (size_t)r * HCn);
            v[3][0] = vv.x; v[3][1] = vv.y; v[3][2] = vv.z; v[3][3] = vv.w;
            al[3][0] = aa.x; al[3][1] = aa.y; al[3][2] = aa.z; al[3][3] = aa.w;
        }
        const float sgate = g_sgate[r];
        float o[4];
        #pragma unroll
        for (int j = 0; j < 4; j++) o[j] = sgate * v[3][j];

        #pragma unroll
        for (int g = 0; g < 4; g++) {
            #pragma unroll
            for (int j = 0; j < 4; j++) {
                const float4 w = wreg[g][j];
                float y = w.x * al[0][g] * v[0][j]
                        + w.y * al[1][g] * v[1][j]
                        + w.z * al[2][g] * v[2][j]
                        + w.w * al[3][g] * v[3][j];
                y *= screg[g][j];
                o[j] += __fdividef(y, 1.f + __expf(-y));
            }
        }
        *(float4*)(out + (size_t)r * HIDn + c) = make_float4(o[0], o[1], o[2], o[3]);

        #pragma unroll
        for (int k = 0; k < 3; k++)
            #pragma unroll
            for (int j = 0; j < 4; j++) { v[k][j] = v[k + 1][j]; al[k][j] = al[k + 1][j]; }
    }
}

// ---------------- host: tensormap construction + launch ----------------
typedef CUresult (*PFN_tmEncode)(
    CUtensorMap*, CUtensorMapDataType, cuuint32_t, void*,
    const cuuint64_t*, const cuuint64_t*, const cuuint32_t*, const cuuint32_t*,
    CUtensorMapInterleave, CUtensorMapSwizzle, CUtensorMapL2promotion,
    CUtensorMapFloatOOBfill);

static void encode_map(PFN_tmEncode fn, CUtensorMap* tm, void* base, unsigned rows)
{
    cuuint64_t dims[2]    = {2048ull, (cuuint64_t)rows};  // bytes per row, rows
    cuuint64_t strides[1] = {2048ull};
    cuuint32_t box[2]     = {128u, 128u};
    cuuint32_t es[2]      = {1u, 1u};
    fn(tm, CU_TENSOR_MAP_DATA_TYPE_UINT8, 2, base, dims, strides, box, es,
       CU_TENSOR_MAP_INTERLEAVE_NONE, CU_TENSOR_MAP_SWIZZLE_128B,
       CU_TENSOR_MAP_L2_PROMOTION_L2_128B, CU_TENSOR_MAP_FLOAT_OOB_FILL_NONE);
}

extern "C" void kernel_launch(void* const* d_in, const int* in_sizes, int n_in,
                              void* d_out, int out_size)
{
    (void)in_sizes; (void)n_in; (void)out_size;
    const float* hid = (const float*)d_in[0];
    const void*  ids = d_in[1];
    const float* tab = (const float*)d_in[2];
    const float* vw  = (const float*)d_in[3];
    const float* vb  = (const float*)d_in[4];
    const float* kw  = (const float*)d_in[5];
    const float* kb  = (const float*)d_in[6];
    const float* n1  = (const float*)d_in[7];
    const float* n2  = (const float*)d_in[8];
    const float* scw = (const float*)d_in[9];
    const float* cw  = (const float*)d_in[10];
    float* out = (float*)d_out;

    PFN_tmEncode fn = nullptr;
    cudaDriverEntryPointQueryResult qres;
    cudaGetDriverEntryPointByVersion("cuTensorMapEncodeTiled", (void**)&fn,
                                     12000, cudaEnableDefault, &qres);
    void *pAh, *pAl, *pBh, *pBl;
    cudaGetSymbolAddress(&pAh, g_embh);
    cudaGetSymbolAddress(&pAl, g_embl);
    cudaGetSymbolAddress(&pBh, g_wth);
    cudaGetSymbolAddress(&pBl, g_wtl);
    CUtensorMap tmAh{}, tmAl{}, tmBh{}, tmBl{};
    if (fn) {
        encode_map(fn, &tmAh, pAh, Mn);
        encode_map(fn, &tmAl, pAl, Mn);
        encode_map(fn, &tmBh, pBh, NTOT);
        encode_map(fn, &tmBl, pBl, NTOT);
    }

    int ccM = 0, ccm = 0, dev = 0;
    cudaGetDevice(&dev);
    cudaDeviceGetAttribute(&ccM, cudaDevAttrComputeCapabilityMajor, dev);
    cudaDeviceGetAttribute(&ccm, cudaDevAttrComputeCapabilityMinor, dev);
    const bool isSm103 = (ccM == 10 && ccm == 3);

    cudaFuncSetAttribute(k_tcgemm,  cudaFuncAttributeMaxDynamicSharedMemorySize, GSMEM);
    cudaFuncSetAttribute(k_gemm_fb, cudaFuncAttributeMaxDynamicSharedMemorySize, FB_SMEM);

    k_prep<<<Mn + (NTOT / 64) * (ENGn / 64), 256>>>(ids, tab, hid, vw, kw);
    if (!isSm103)
        k_gemm_fb<<<dim3(80, 64), 256, FB_SMEM>>>(vb, kb, n1, n2, hid);
    k_tcgemm<<<dim3(64, 20), 256, GSMEM>>>(tmAh, tmAl, tmBh, tmBl,
                                           vb, kb, n1, n2, hid);
    k_gate<<<Mn, 32>>>();
    {
        const int nchunks = ((Ln + 2) / 3 + SCHUNK - 1) / SCHUNK;   // 86
        k_out<<<dim3(2, nchunks, 2 * 3), 256>>>(scw, cw, out);
    }
}